// round 11
// baseline (speedup 1.0000x reference)
#include <cuda_runtime.h>
#include <cuda_fp16.h>
#include <cstdint>

#define BB 8
#define CC 512
#define TT 2048
#define EE 512
#define LN_EPS 1e-5f

typedef __half f16;

// ------------------------------------------------------------------
// scratch (device globals — allocation-free rule)
// ------------------------------------------------------------------
__device__ float g_resid[BB * TT * CC];
__device__ f16   g_resid_h[BB * TT * CC];
__device__ f16   g_resid_l[BB * TT * CC];
__device__ f16   g_qm_h[BB * TT * CC];     // qm = resid @ M
__device__ f16   g_qm_l[BB * TT * CC];
__device__ f16   g_vt_h[BB * CC * TT];     // vw transposed: [B][C][T] (h only)
__device__ f16   g_attn_h[(size_t)BB * TT * TT];
__device__ float g_h[BB * TT * CC];
// weight splits
__device__ f16   g_wq_h[CC * EE], g_wq_l[CC * EE];     // Wq split [C,E]
__device__ f16   g_wk_h[CC * EE], g_wk_l[CC * EE];     // Wk split [C,E]
__device__ f16   g_wv_h[CC * EE], g_wv_l[CC * EE];     // Wv split [C,E]
__device__ f16   g_woT_h[CC * EE], g_woT_l[CC * EE];   // Wo^T split [C,E]
// fused weight products (split)
__device__ f16   g_MT_h[CC * CC], g_MT_l[CC * CC];     // MT = Wk @ Wq^T
__device__ f16   g_NT_h[CC * CC], g_NT_l[CC * CC];     // NT = Wo^T @ Wv^T
// bias-correction vectors
__device__ float g_vqk[CC];     // Wq @ bk
__device__ float g_vkq[CC];     // Wk @ bq
__device__ float g_bvo[CC];     // Wo^T @ bv
__device__ float g_u[BB * TT];  // resid @ vqk + bq.bk
__device__ float g_w[BB * TT];  // resid @ vkq
__device__ float g_scal[1];     // bq . bk
__device__ float g_zero_s[1];   // stays 0

// ------------------------------------------------------------------
// low-level helpers
// ------------------------------------------------------------------
__device__ __forceinline__ uint32_t smem_u32(const void* p) {
    uint32_t a;
    asm("{ .reg .u64 t; cvta.to.shared.u64 t, %1; cvt.u32.u64 %0, t; }" : "=r"(a) : "l"(p));
    return a;
}

__device__ __forceinline__ uint32_t swz64(uint32_t o) { return o ^ ((o >> 3) & 0x30); }

#define CP16(dst, src) \
    asm volatile("cp.async.cg.shared.global [%0], [%1], 16;" :: "r"(dst), "l"(src))
#define CP_COMMIT() asm volatile("cp.async.commit_group;" ::: "memory")
#define CP_WAIT(n)  asm volatile("cp.async.wait_group %0;" :: "n"(n) : "memory")

__device__ __forceinline__ void ldsm4(uint32_t* r, uint32_t addr) {
    asm volatile("ldmatrix.sync.aligned.m8n8.x4.shared.b16 {%0,%1,%2,%3}, [%4];"
                 : "=r"(r[0]), "=r"(r[1]), "=r"(r[2]), "=r"(r[3]) : "r"(addr));
}

__device__ __forceinline__ void mma_f16(float* c, const uint32_t* a,
                                        uint32_t b0, uint32_t b1) {
    asm("mma.sync.aligned.m16n8k16.row.col.f32.f16.f16.f32 "
        "{%0,%1,%2,%3}, {%4,%5,%6,%7}, {%8,%9}, {%0,%1,%2,%3};"
        : "+f"(c[0]), "+f"(c[1]), "+f"(c[2]), "+f"(c[3])
        : "r"(a[0]), "r"(a[1]), "r"(a[2]), "r"(a[3]), "r"(b0), "r"(b1));
}

__device__ __forceinline__ void split2(float v, f16& h, f16& l) {
    h = __float2half(v);
    l = __float2half(v - __half2float(h));
}

// ------------------------------------------------------------------
// HMMA GEMM: D[128m x 128n] = selected terms of (Ah+Al)·(Bh+Bl)^T
// Terms: AhBh always; + AhBl if USE_BL; + AlBh if USE_AL.
// ------------------------------------------------------------------
#define TILE_B (128 * 32 * 2)
#define CHUNK_B (4 * TILE_B)
#define NSTAGE 3
#define GEMM_SMEM_REQ (NSTAGE * CHUNK_B)

enum { EPI_F32 = 0, EPI_SPLIT = 3, EPI_F32_BIAS_RES = 4, EPI_F32_UW = 5, EPI_BIAS_T_H = 6 };

template <int EPI, int USE_AL, int USE_BL>
__global__ __launch_bounds__(512)
void hmma_gemm(const f16* __restrict__ Ah, const f16* __restrict__ Al, int ldA, size_t sA,
               const f16* __restrict__ Bh, const f16* __restrict__ Bl, int ldB, size_t sB,
               const float* __restrict__ bias, const float* __restrict__ res,
               const float* __restrict__ uvec, const float* __restrict__ wvec,
               float* __restrict__ Cf, f16* __restrict__ Ch, f16* __restrict__ Cl,
               int ldc, size_t sC, int K) {
    extern __shared__ char sm[];
    uint32_t smu = smem_u32(sm);

    const int tid = threadIdx.x;
    const int w = tid >> 5, lane = tid & 31;
    const int bz = blockIdx.z;
    const int m0 = blockIdx.y * 128;
    const int n0 = blockIdx.x * 128;

    const f16* pAh = Ah + (size_t)bz * sA + (size_t)m0 * ldA;
    const f16* pAl = USE_AL ? (Al + (size_t)bz * sA + (size_t)m0 * ldA) : nullptr;
    const f16* pBh = Bh + (size_t)bz * sB + (size_t)n0 * ldB;
    const f16* pBl = USE_BL ? (Bl + (size_t)bz * sB + (size_t)n0 * ldB) : nullptr;

    const int lrow = tid >> 2, lcs = tid & 3;
    const uint32_t loff = swz64((uint32_t)(lrow * 64 + lcs * 16));
    auto load_chunk = [&](int buf, int k0) {
        uint32_t base = smu + (uint32_t)buf * CHUNK_B;
        CP16(base + 0 * TILE_B + loff, pAh + (size_t)lrow * ldA + k0 + lcs * 8);
        if (USE_AL) CP16(base + 1 * TILE_B + loff, pAl + (size_t)lrow * ldA + k0 + lcs * 8);
        CP16(base + 2 * TILE_B + loff, pBh + (size_t)lrow * ldB + k0 + lcs * 8);
        if (USE_BL) CP16(base + 3 * TILE_B + loff, pBl + (size_t)lrow * ldB + k0 + lcs * 8);
    };

    const int wm = w >> 2, wn = w & 3;
    const int lr = lane & 7;
    const int r8 = (lane >> 3) & 1;
    const int chi = lane >> 4;

    uint32_t offA[2][2], offB[2][2];
#pragma unroll
    for (int mt = 0; mt < 2; mt++)
#pragma unroll
        for (int ks = 0; ks < 2; ks++)
            offA[mt][ks] = swz64((uint32_t)((wm * 32 + mt * 16 + r8 * 8 + lr) * 64 + (2 * ks + chi) * 16));
#pragma unroll
    for (int nt = 0; nt < 2; nt++)
#pragma unroll
        for (int ks = 0; ks < 2; ks++)
            offB[nt][ks] = swz64((uint32_t)((wn * 32 + nt * 16 + r8 * 8 + lr) * 64 + (2 * ks + chi) * 16));

    float acc[2][4][4];
#pragma unroll
    for (int i = 0; i < 2; i++)
#pragma unroll
        for (int j = 0; j < 4; j++)
#pragma unroll
            for (int q = 0; q < 4; q++) acc[i][j][q] = 0.f;

    const int nch = K / 32;
    load_chunk(0, 0);
    CP_COMMIT();
    if (nch > 1) load_chunk(1, 32);
    CP_COMMIT();

    int buf = 0;
    for (int c = 0; c < nch; c++) {
        CP_WAIT(1);
        __syncthreads();

        if (c + 2 < nch) {
            int fb = buf + 2;
            if (fb >= NSTAGE) fb -= NSTAGE;
            load_chunk(fb, (c + 2) * 32);
        }
        CP_COMMIT();

        uint32_t bu = smu + (uint32_t)buf * CHUNK_B;
#pragma unroll
        for (int ks = 0; ks < 2; ks++) {
            uint32_t afh[2][4], afl[2][4], bfh[2][4], bfl[2][4];
#pragma unroll
            for (int mt = 0; mt < 2; mt++) {
                ldsm4(afh[mt], bu + 0 * TILE_B + offA[mt][ks]);
                if (USE_AL) ldsm4(afl[mt], bu + 1 * TILE_B + offA[mt][ks]);
            }
#pragma unroll
            for (int nt = 0; nt < 2; nt++) {
                ldsm4(bfh[nt], bu + 2 * TILE_B + offB[nt][ks]);
                if (USE_BL) ldsm4(bfl[nt], bu + 3 * TILE_B + offB[nt][ks]);
            }
#pragma unroll
            for (int mt = 0; mt < 2; mt++)
#pragma unroll
                for (int nt = 0; nt < 2; nt++) {
                    mma_f16(acc[mt][nt * 2 + 0], afh[mt], bfh[nt][0], bfh[nt][2]);
                    mma_f16(acc[mt][nt * 2 + 1], afh[mt], bfh[nt][1], bfh[nt][3]);
                }
            if (USE_BL) {
#pragma unroll
                for (int mt = 0; mt < 2; mt++)
#pragma unroll
                    for (int nt = 0; nt < 2; nt++) {
                        mma_f16(acc[mt][nt * 2 + 0], afh[mt], bfl[nt][0], bfl[nt][2]);
                        mma_f16(acc[mt][nt * 2 + 1], afh[mt], bfl[nt][1], bfl[nt][3]);
                    }
            }
            if (USE_AL) {
#pragma unroll
                for (int mt = 0; mt < 2; mt++)
#pragma unroll
                    for (int nt = 0; nt < 2; nt++) {
                        mma_f16(acc[mt][nt * 2 + 0], afl[mt], bfh[nt][0], bfh[nt][2]);
                        mma_f16(acc[mt][nt * 2 + 1], afl[mt], bfh[nt][1], bfh[nt][3]);
                    }
            }
        }
        buf++;
        if (buf == NSTAGE) buf = 0;
    }
    __syncthreads();

    // ---- epilogue: accumulators -> staged smem [128][129] fp32 -> gmem ----
    float* st = (float*)sm;
    {
        int g = lane >> 2, t4 = lane & 3;
#pragma unroll
        for (int mt = 0; mt < 2; mt++) {
            int r = wm * 32 + mt * 16 + g;
#pragma unroll
            for (int j = 0; j < 4; j++) {
                int ccol = wn * 32 + j * 8 + 2 * t4;
                st[r * 129 + ccol]           = acc[mt][j][0];
                st[r * 129 + ccol + 1]       = acc[mt][j][1];
                st[(r + 8) * 129 + ccol]     = acc[mt][j][2];
                st[(r + 8) * 129 + ccol + 1] = acc[mt][j][3];
            }
        }
    }
    __syncthreads();

    if (EPI == EPI_BIAS_T_H) {
        // transposed h-only store + bias: dest [b][c][t]
#pragma unroll 4
        for (int it = 0; it < 8; it++) {
            int col = w + 16 * it;
            float bvv = bias[n0 + col];
#pragma unroll
            for (int j = 0; j < 4; j++) {
                int row = lane + 32 * j;
                float v = st[row * 129 + col] + bvv;
                size_t m = (size_t)m0 + row;
                int bb_ = (int)(m / TT);
                int t = (int)(m % TT);
                size_t off = ((size_t)bb_ * CC + (n0 + col)) * TT + t;
                Ch[off] = __float2half(v);
            }
        }
    } else if (EPI == EPI_F32_UW) {
#pragma unroll 2
        for (int rr = 0; rr < 8; rr++) {
            int row = w * 8 + rr;
            size_t m = (size_t)m0 + row;
            float um = uvec[(size_t)bz * TT + m];
#pragma unroll
            for (int cb = 0; cb < 4; cb++) {
                int col = lane + 32 * cb;
                float wn_ = wvec[(size_t)bz * TT + n0 + col];
                Cf[(size_t)bz * sC + m * ldc + n0 + col] = st[row * 129 + col] + um + wn_;
            }
        }
    } else {
        const float* resb = (EPI == EPI_F32_BIAS_RES) ? (res + (size_t)bz * sC) : nullptr;
        float bvv[4];
#pragma unroll
        for (int cb = 0; cb < 4; cb++)
            bvv[cb] = (EPI == EPI_F32_BIAS_RES) ? bias[n0 + lane + 32 * cb] : 0.f;

#pragma unroll 2
        for (int rr = 0; rr < 8; rr++) {
            int row = w * 8 + rr;
            size_t m = (size_t)m0 + row;
#pragma unroll
            for (int cb = 0; cb < 4; cb++) {
                int col = lane + 32 * cb;
                float v = st[row * 129 + col] + bvv[cb];
                size_t off = (size_t)bz * sC + m * ldc + n0 + col;
                if (EPI == EPI_F32) {
                    Cf[off] = v;
                } else if (EPI == EPI_F32_BIAS_RES) {
                    Cf[off] = v + resb[m * ldc + n0 + col];
                } else {  // EPI_SPLIT
                    f16 h, l; split2(v, h, l);
                    Ch[off] = h;
                    Cl[off] = l;
                }
            }
        }
    }
}

// ------------------------------------------------------------------
// transpose + split: x[B,C,T] -> resid[B,T,C] (fp32 + hi/lo fp16)
// ------------------------------------------------------------------
__global__ __launch_bounds__(256)
void transpose_split(const float* __restrict__ x, float* __restrict__ r,
                     f16* __restrict__ rh, f16* __restrict__ rl) {
    __shared__ float tile[32][33];
    int b = blockIdx.z;
    int t0 = blockIdx.x * 32;
    int c0 = blockIdx.y * 32;
    const float* xb = x + (size_t)b * CC * TT;
    size_t ob = (size_t)b * TT * CC;
    int tx = threadIdx.x, ty = threadIdx.y;
#pragma unroll
    for (int i = ty; i < 32; i += 8)
        tile[i][tx] = xb[(size_t)(c0 + i) * TT + t0 + tx];
    __syncthreads();
#pragma unroll
    for (int i = ty; i < 32; i += 8) {
        float v = tile[tx][i];
        size_t off = ob + (size_t)(t0 + i) * CC + c0 + tx;
        r[off] = v;
        f16 h, l; split2(v, h, l);
        rh[off] = h;
        rl[off] = l;
    }
}

// elementwise split W [512*512]
__global__ __launch_bounds__(256)
void splitW(const float* __restrict__ W, f16* __restrict__ Th, f16* __restrict__ Tl) {
    int i = blockIdx.x * 256 + threadIdx.x;
    float v = W[i];
    f16 h, l; split2(v, h, l);
    Th[i] = h;
    Tl[i] = l;
}

// W [512,512] -> W^T hi/lo (used for Wo)
__global__ __launch_bounds__(256)
void wsplit(const float* __restrict__ W, f16* __restrict__ Th, f16* __restrict__ Tl) {
    __shared__ float tile[32][33];
    int k0 = blockIdx.y * 32, n0 = blockIdx.x * 32;
    int tx = threadIdx.x, ty = threadIdx.y;
#pragma unroll
    for (int i = ty; i < 32; i += 8)
        tile[i][tx] = W[(size_t)(k0 + i) * 512 + n0 + tx];
    __syncthreads();
#pragma unroll
    for (int i = ty; i < 32; i += 8) {
        float v = tile[tx][i];
        size_t off = (size_t)(n0 + i) * 512 + k0 + tx;
        f16 h, l; split2(v, h, l);
        Th[off] = h;
        Tl[off] = l;
    }
}

// ---- small bias-path kernels ----
__global__ void dotk(const float* __restrict__ a, const float* __restrict__ b,
                     float* __restrict__ outscal) {
    int lane = threadIdx.x;
    float s = 0.f;
    for (int i = lane; i < 512; i += 32) s += a[i] * b[i];
#pragma unroll
    for (int o = 16; o; o >>= 1) s += __shfl_xor_sync(0xffffffffu, s, o);
    if (lane == 0) outscal[0] = s;
}

__global__ __launch_bounds__(256)
void matvec_row(const float* __restrict__ A, const float* __restrict__ v,
                float* __restrict__ out) {
    int c = blockIdx.x * 8 + (threadIdx.x >> 5);
    int lane = threadIdx.x & 31;
    float s = 0.f;
    for (int e = lane; e < 512; e += 32) s += A[(size_t)c * 512 + e] * v[e];
#pragma unroll
    for (int o = 16; o; o >>= 1) s += __shfl_xor_sync(0xffffffffu, s, o);
    if (lane == 0) out[c] = s;
}

__global__ __launch_bounds__(256)
void matvec_row_hf(const f16* __restrict__ Th, const f16* __restrict__ Tl,
                   const float* __restrict__ v, float* __restrict__ out) {
    int c = blockIdx.x * 8 + (threadIdx.x >> 5);
    int lane = threadIdx.x & 31;
    float s = 0.f;
    for (int e = lane; e < 512; e += 32) {
        float wv = __half2float(Th[(size_t)c * 512 + e]) +
                   __half2float(Tl[(size_t)c * 512 + e]);
        s += wv * v[e];
    }
#pragma unroll
    for (int o = 16; o; o >>= 1) s += __shfl_xor_sync(0xffffffffu, s, o);
    if (lane == 0) out[c] = s;
}

__global__ __launch_bounds__(256)
void rowdot(const float* __restrict__ r, const float* __restrict__ vv,
            const float* __restrict__ scal, float* __restrict__ u) {
    int row = blockIdx.x * 8 + (threadIdx.x >> 5);
    int lane = threadIdx.x & 31;
    float s = 0.f;
    for (int c = lane; c < 512; c += 32) s += r[(size_t)row * 512 + c] * vv[c];
#pragma unroll
    for (int o = 16; o; o >>= 1) s += __shfl_xor_sync(0xffffffffu, s, o);
    if (lane == 0) u[row] = s + scal[0];
}

// ------------------------------------------------------------------
// softmax (in-place fp32) + emit fp16
// ------------------------------------------------------------------
__global__ __launch_bounds__(256)
void softmax_split(float* __restrict__ attn, f16* __restrict__ ah) {
    size_t ro = (size_t)blockIdx.x * TT;
    float* row = attn + ro;
    int t = threadIdx.x;
    float vals[8];
    float m = -1e30f;
#pragma unroll
    for (int j = 0; j < 8; j++) {
        vals[j] = row[t + 256 * j];
        m = fmaxf(m, vals[j]);
    }
#pragma unroll
    for (int o = 16; o; o >>= 1) m = fmaxf(m, __shfl_xor_sync(0xffffffffu, m, o));
    __shared__ float smax[8], ssum[8];
    if ((t & 31) == 0) smax[t >> 5] = m;
    __syncthreads();
    float rm = smax[0];
#pragma unroll
    for (int i = 1; i < 8; i++) rm = fmaxf(rm, smax[i]);

    float s = 0.f;
#pragma unroll
    for (int j = 0; j < 8; j++) {
        vals[j] = expf(vals[j] - rm);
        s += vals[j];
    }
#pragma unroll
    for (int o = 16; o; o >>= 1) s += __shfl_xor_sync(0xffffffffu, s, o);
    if ((t & 31) == 0) ssum[t >> 5] = s;
    __syncthreads();
    float tot = 0.f;
#pragma unroll
    for (int i = 0; i < 8; i++) tot += ssum[i];
    float inv = 1.f / tot;

#pragma unroll
    for (int j = 0; j < 8; j++) {
        float v = vals[j] * inv;
        row[t + 256 * j] = v;
        ah[ro + t + 256 * j] = __float2half(v);
    }
}

// ------------------------------------------------------------------
// LayerNorm over C=512
// ------------------------------------------------------------------
__global__ __launch_bounds__(128)
void ln_kernel(const float* __restrict__ h, const float* __restrict__ gamma,
               const float* __restrict__ beta, float* __restrict__ out) {
    const float* hr = h + (size_t)blockIdx.x * CC;
    int t = threadIdx.x;
    float4 v = ((const float4*)hr)[t];

    float s = v.x + v.y + v.z + v.w;
#pragma unroll
    for (int o = 16; o; o >>= 1) s += __shfl_xor_sync(0xffffffffu, s, o);
    __shared__ float s1[4], s2[4];
    if ((t & 31) == 0) s1[t >> 5] = s;
    __syncthreads();
    float mu = (s1[0] + s1[1] + s1[2] + s1[3]) * (1.f / CC);

    float dx = v.x - mu, dy = v.y - mu, dz = v.z - mu, dw = v.w - mu;
    float q = dx * dx + dy * dy + dz * dz + dw * dw;
#pragma unroll
    for (int o = 16; o; o >>= 1) q += __shfl_xor_sync(0xffffffffu, q, o);
    if ((t & 31) == 0) s2[t >> 5] = q;
    __syncthreads();
    float var = (s2[0] + s2[1] + s2[2] + s2[3]) * (1.f / CC);
    float inv = rsqrtf(var + LN_EPS);

    float4 g = ((const float4*)gamma)[t];
    float4 b = ((const float4*)beta)[t];
    float4 o4;
    o4.x = dx * inv * g.x + b.x;
    o4.y = dy * inv * g.y + b.y;
    o4.z = dz * inv * g.z + b.z;
    o4.w = dw * inv * g.w + b.w;
    ((float4*)(out + (size_t)blockIdx.x * CC))[t] = o4;
}

// ------------------------------------------------------------------
// launch
// ------------------------------------------------------------------
extern "C" void kernel_launch(void* const* d_in, const int* in_sizes, int n_in,
                              void* d_out, int out_size) {
    const float* x     = (const float*)d_in[0];
    const float* Wq    = (const float*)d_in[1];
    const float* bq    = (const float*)d_in[2];
    const float* Wk    = (const float*)d_in[3];
    const float* bk    = (const float*)d_in[4];
    const float* Wv    = (const float*)d_in[5];
    const float* bv    = (const float*)d_in[6];
    const float* Wo    = (const float*)d_in[7];
    const float* bo    = (const float*)d_in[8];
    const float* gamma = (const float*)d_in[9];
    const float* beta  = (const float*)d_in[10];

    float* out = (float*)d_out;
    float* attn = out;
    float* final_out = out + (size_t)BB * TT * TT;

    float *resid, *hbuf, *vqk, *vkq, *bvo, *uv, *wv_, *scal, *zero_s;
    f16 *rh, *rl, *qmh, *qml, *vth, *anh;
    f16 *wqh, *wql, *wkh, *wkl, *wvh, *wvl, *woh, *wol;
    f16 *mth, *mtl, *nth, *ntl;
    cudaGetSymbolAddress((void**)&resid, g_resid);
    cudaGetSymbolAddress((void**)&hbuf, g_h);
    cudaGetSymbolAddress((void**)&rh, g_resid_h);
    cudaGetSymbolAddress((void**)&rl, g_resid_l);
    cudaGetSymbolAddress((void**)&qmh, g_qm_h);
    cudaGetSymbolAddress((void**)&qml, g_qm_l);
    cudaGetSymbolAddress((void**)&vth, g_vt_h);
    cudaGetSymbolAddress((void**)&anh, g_attn_h);
    cudaGetSymbolAddress((void**)&wqh, g_wq_h);
    cudaGetSymbolAddress((void**)&wql, g_wq_l);
    cudaGetSymbolAddress((void**)&wkh, g_wk_h);
    cudaGetSymbolAddress((void**)&wkl, g_wk_l);
    cudaGetSymbolAddress((void**)&wvh, g_wv_h);
    cudaGetSymbolAddress((void**)&wvl, g_wv_l);
    cudaGetSymbolAddress((void**)&woh, g_woT_h);
    cudaGetSymbolAddress((void**)&wol, g_woT_l);
    cudaGetSymbolAddress((void**)&mth, g_MT_h);
    cudaGetSymbolAddress((void**)&mtl, g_MT_l);
    cudaGetSymbolAddress((void**)&nth, g_NT_h);
    cudaGetSymbolAddress((void**)&ntl, g_NT_l);
    cudaGetSymbolAddress((void**)&vqk, g_vqk);
    cudaGetSymbolAddress((void**)&vkq, g_vkq);
    cudaGetSymbolAddress((void**)&bvo, g_bvo);
    cudaGetSymbolAddress((void**)&uv, g_u);
    cudaGetSymbolAddress((void**)&wv_, g_w);
    cudaGetSymbolAddress((void**)&scal, g_scal);
    cudaGetSymbolAddress((void**)&zero_s, g_zero_s);

    cudaFuncSetAttribute(hmma_gemm<EPI_SPLIT, 1, 1>,       cudaFuncAttributeMaxDynamicSharedMemorySize, GEMM_SMEM_REQ);
    cudaFuncSetAttribute(hmma_gemm<EPI_SPLIT, 1, 0>,       cudaFuncAttributeMaxDynamicSharedMemorySize, GEMM_SMEM_REQ);
    cudaFuncSetAttribute(hmma_gemm<EPI_F32_UW, 1, 1>,      cudaFuncAttributeMaxDynamicSharedMemorySize, GEMM_SMEM_REQ);
    cudaFuncSetAttribute(hmma_gemm<EPI_BIAS_T_H, 0, 0>,    cudaFuncAttributeMaxDynamicSharedMemorySize, GEMM_SMEM_REQ);
    cudaFuncSetAttribute(hmma_gemm<EPI_F32_BIAS_RES, 0, 0>, cudaFuncAttributeMaxDynamicSharedMemorySize, GEMM_SMEM_REQ);

    // ---- prep: transpose + weight splits ----
    transpose_split<<<dim3(TT / 32, CC / 32, BB), dim3(32, 8)>>>(x, resid, rh, rl);
    splitW<<<1024, 256>>>(Wq, wqh, wql);
    splitW<<<1024, 256>>>(Wk, wkh, wkl);
    splitW<<<1024, 256>>>(Wv, wvh, wvl);
    wsplit<<<dim3(16, 16), dim3(32, 8)>>>(Wo, woh, wol);

    // bias-correction vectors (exact)
    dotk<<<1, 32>>>(bq, bk, scal);
    matvec_row<<<64, 256>>>(Wq, bk, vqk);
    matvec_row<<<64, 256>>>(Wk, bq, vkq);
    matvec_row_hf<<<64, 256>>>(woh, wol, bv, bvo);
    rowdot<<<(BB * TT) / 8, 256>>>(resid, vqk, scal, uv);     // u = r@vqk + bq.bk
    rowdot<<<(BB * TT) / 8, 256>>>(resid, vkq, zero_s, wv_);  // w = r@vkq

    // MT = Wk @ Wq^T, NT = Wo^T @ Wv^T — tiny 3-term GEMMs
    hmma_gemm<EPI_SPLIT, 1, 1><<<dim3(4, 4, 1), 512, GEMM_SMEM_REQ>>>(
        wkh, wkl, EE, 0, wqh, wql, EE, 0, nullptr, nullptr, nullptr, nullptr,
        nullptr, mth, mtl, CC, 0, EE);
    hmma_gemm<EPI_SPLIT, 1, 1><<<dim3(4, 4, 1), 512, GEMM_SMEM_REQ>>>(
        woh, wol, EE, 0, wvh, wvl, EE, 0, nullptr, nullptr, nullptr, nullptr,
        nullptr, nth, ntl, CC, 0, EE);

    // qm = resid @ M   (2-term: (rh+rl)·Mh; fp16 split out)
    hmma_gemm<EPI_SPLIT, 1, 0><<<dim3(CC / 128, (BB * TT) / 128, 1), 512, GEMM_SMEM_REQ>>>(
        rh, rl, CC, 0, mth, nullptr, CC, 0, nullptr, nullptr, nullptr, nullptr,
        nullptr, qmh, qml, CC, 0, CC);

    // energy = qm @ resid^T + u[t] + w[s]  (3-term) -> fp32 logits in attn region
    hmma_gemm<EPI_F32_UW, 1, 1><<<dim3(TT / 128, TT / 128, BB), 512, GEMM_SMEM_REQ>>>(
        qmh, qml, CC, (size_t)TT * CC, rh, rl, CC, (size_t)TT * CC,
        nullptr, nullptr, uv, wv_,
        attn, nullptr, nullptr, TT, (size_t)TT * TT, CC);

    // softmax in-place + emit fp16
    softmax_split<<<BB * TT, 256>>>(attn, anh);

    // vw = resid @ N + bvo   (1-term; transposed h-only out -> [B][C][T])
    hmma_gemm<EPI_BIAS_T_H, 0, 0><<<dim3(CC / 128, (BB * TT) / 128, 1), 512, GEMM_SMEM_REQ>>>(
        rh, nullptr, CC, 0, nth, nullptr, CC, 0, bvo, nullptr, nullptr, nullptr,
        nullptr, vth, nullptr, CC, 0, CC);

    // h = attn_h @ vw^T + bo + resid   (1-term)
    hmma_gemm<EPI_F32_BIAS_RES, 0, 0><<<dim3(CC / 128, TT / 128, BB), 512, GEMM_SMEM_REQ>>>(
        anh, nullptr, TT, (size_t)TT * TT, vth, nullptr, TT, (size_t)CC * TT,
        bo, resid, nullptr, nullptr,
        hbuf, nullptr, nullptr, CC, (size_t)TT * CC, TT);

    // LayerNorm -> final output region
    ln_kernel<<<BB * TT, 128>>>(hbuf, gamma, beta, final_out);
}

// round 12
// speedup vs baseline: 1.4229x; 1.4229x over previous
#include <cuda_runtime.h>
#include <cuda_bf16.h>
#include <cstdint>

#define BB 8
#define CC 512
#define TT 2048
#define EE 512
#define LN_EPS 1e-5f

typedef __nv_bfloat16 bf16;

// ------------------------------------------------------------------
// scratch (device globals — allocation-free rule)
// ------------------------------------------------------------------
__device__ float g_resid[BB * TT * CC];
__device__ bf16  g_resid_h[BB * TT * CC];
__device__ bf16  g_resid_l[BB * TT * CC];
__device__ bf16  g_qm_h[BB * TT * CC];     // qm = resid @ M
__device__ bf16  g_qm_l[BB * TT * CC];
__device__ bf16  g_vt_h[BB * CC * TT];     // vw transposed: [B][C][T] (h only)
__device__ bf16  g_attn_h[(size_t)BB * TT * TT];
__device__ float g_h[BB * TT * CC];
// weight splits
__device__ bf16  g_wq_h[CC * EE], g_wq_l[CC * EE];     // Wq split [C,E]
__device__ bf16  g_wk_h[CC * EE], g_wk_l[CC * EE];     // Wk split [C,E]
__device__ bf16  g_wv_h[CC * EE], g_wv_l[CC * EE];     // Wv split [C,E]
__device__ bf16  g_woT_h[CC * EE], g_woT_l[CC * EE];   // Wo^T split [C,E]
// fused weight products (split)
__device__ bf16  g_MT_h[CC * CC], g_MT_l[CC * CC];     // MT = Wk @ Wq^T
__device__ bf16  g_NT_h[CC * CC], g_NT_l[CC * CC];     // NT = Wo^T @ Wv^T
// bias-correction vectors
__device__ float g_vqk[CC];     // Wq @ bk
__device__ float g_vkq[CC];     // Wk @ bq
__device__ float g_bvo[CC];     // Wo^T @ bv
__device__ float g_u[BB * TT];  // resid @ vqk + bq.bk
__device__ float g_w[BB * TT];  // resid @ vkq
__device__ float g_scal[1];     // bq . bk
__device__ float g_zero_s[1];   // stays 0

// ------------------------------------------------------------------
// low-level helpers
// ------------------------------------------------------------------
__device__ __forceinline__ uint32_t smem_u32(const void* p) {
    uint32_t a;
    asm("{ .reg .u64 t; cvta.to.shared.u64 t, %1; cvt.u32.u64 %0, t; }" : "=r"(a) : "l"(p));
    return a;
}

__device__ __forceinline__ uint32_t swz64(uint32_t o) { return o ^ ((o >> 3) & 0x30); }

#define CP16(dst, src) \
    asm volatile("cp.async.cg.shared.global [%0], [%1], 16;" :: "r"(dst), "l"(src))
#define CP_COMMIT() asm volatile("cp.async.commit_group;" ::: "memory")
#define CP_WAIT(n)  asm volatile("cp.async.wait_group %0;" :: "n"(n) : "memory")

__device__ __forceinline__ void ldsm4(uint32_t* r, uint32_t addr) {
    asm volatile("ldmatrix.sync.aligned.m8n8.x4.shared.b16 {%0,%1,%2,%3}, [%4];"
                 : "=r"(r[0]), "=r"(r[1]), "=r"(r[2]), "=r"(r[3]) : "r"(addr));
}

__device__ __forceinline__ void mma_bf16(float* c, const uint32_t* a,
                                         uint32_t b0, uint32_t b1) {
    asm("mma.sync.aligned.m16n8k16.row.col.f32.bf16.bf16.f32 "
        "{%0,%1,%2,%3}, {%4,%5,%6,%7}, {%8,%9}, {%0,%1,%2,%3};"
        : "+f"(c[0]), "+f"(c[1]), "+f"(c[2]), "+f"(c[3])
        : "r"(a[0]), "r"(a[1]), "r"(a[2]), "r"(a[3]), "r"(b0), "r"(b1));
}

__device__ __forceinline__ void split2(float v, bf16& h, bf16& l) {
    h = __float2bfloat16(v);
    l = __float2bfloat16(v - __bfloat162float(h));
}

// ------------------------------------------------------------------
// HMMA GEMM: D[128m x 128n] = selected terms of (Ah+Al)·(Bh+Bl)^T
// ------------------------------------------------------------------
#define TILE_B (128 * 32 * 2)
#define CHUNK_B (4 * TILE_B)
#define NSTAGE 3
#define GEMM_SMEM_REQ (NSTAGE * CHUNK_B)

enum { EPI_F32 = 0, EPI_SPLIT = 3, EPI_F32_BIAS_RES = 4, EPI_F32_UW = 5, EPI_BIAS_T_H = 6 };

template <int EPI, int USE_AL, int USE_BL>
__global__ __launch_bounds__(512)
void hmma_gemm(const bf16* __restrict__ Ah, const bf16* __restrict__ Al, int ldA, size_t sA,
               const bf16* __restrict__ Bh, const bf16* __restrict__ Bl, int ldB, size_t sB,
               const float* __restrict__ bias, const float* __restrict__ res,
               const float* __restrict__ uvec, const float* __restrict__ wvec,
               float* __restrict__ Cf, bf16* __restrict__ Ch, bf16* __restrict__ Cl,
               int ldc, size_t sC, int K) {
    extern __shared__ char sm[];
    uint32_t smu = smem_u32(sm);

    const int tid = threadIdx.x;
    const int w = tid >> 5, lane = tid & 31;
    const int bz = blockIdx.z;
    const int m0 = blockIdx.y * 128;
    const int n0 = blockIdx.x * 128;

    const bf16* pAh = Ah + (size_t)bz * sA + (size_t)m0 * ldA;
    const bf16* pAl = USE_AL ? (Al + (size_t)bz * sA + (size_t)m0 * ldA) : nullptr;
    const bf16* pBh = Bh + (size_t)bz * sB + (size_t)n0 * ldB;
    const bf16* pBl = USE_BL ? (Bl + (size_t)bz * sB + (size_t)n0 * ldB) : nullptr;

    const int lrow = tid >> 2, lcs = tid & 3;
    const uint32_t loff = swz64((uint32_t)(lrow * 64 + lcs * 16));
    auto load_chunk = [&](int buf, int k0) {
        uint32_t base = smu + (uint32_t)buf * CHUNK_B;
        CP16(base + 0 * TILE_B + loff, pAh + (size_t)lrow * ldA + k0 + lcs * 8);
        if (USE_AL) CP16(base + 1 * TILE_B + loff, pAl + (size_t)lrow * ldA + k0 + lcs * 8);
        CP16(base + 2 * TILE_B + loff, pBh + (size_t)lrow * ldB + k0 + lcs * 8);
        if (USE_BL) CP16(base + 3 * TILE_B + loff, pBl + (size_t)lrow * ldB + k0 + lcs * 8);
    };

    const int wm = w >> 2, wn = w & 3;
    const int lr = lane & 7;
    const int r8 = (lane >> 3) & 1;
    const int chi = lane >> 4;

    uint32_t offA[2][2], offB[2][2];
#pragma unroll
    for (int mt = 0; mt < 2; mt++)
#pragma unroll
        for (int ks = 0; ks < 2; ks++)
            offA[mt][ks] = swz64((uint32_t)((wm * 32 + mt * 16 + r8 * 8 + lr) * 64 + (2 * ks + chi) * 16));
#pragma unroll
    for (int nt = 0; nt < 2; nt++)
#pragma unroll
        for (int ks = 0; ks < 2; ks++)
            offB[nt][ks] = swz64((uint32_t)((wn * 32 + nt * 16 + r8 * 8 + lr) * 64 + (2 * ks + chi) * 16));

    float acc[2][4][4];
#pragma unroll
    for (int i = 0; i < 2; i++)
#pragma unroll
        for (int j = 0; j < 4; j++)
#pragma unroll
            for (int q = 0; q < 4; q++) acc[i][j][q] = 0.f;

    const int nch = K / 32;
    load_chunk(0, 0);
    CP_COMMIT();
    if (nch > 1) load_chunk(1, 32);
    CP_COMMIT();

    int buf = 0;
    for (int c = 0; c < nch; c++) {
        CP_WAIT(1);
        __syncthreads();

        if (c + 2 < nch) {
            int fb = buf + 2;
            if (fb >= NSTAGE) fb -= NSTAGE;
            load_chunk(fb, (c + 2) * 32);
        }
        CP_COMMIT();

        uint32_t bu = smu + (uint32_t)buf * CHUNK_B;
#pragma unroll
        for (int ks = 0; ks < 2; ks++) {
            uint32_t afh[2][4], afl[2][4], bfh[2][4], bfl[2][4];
#pragma unroll
            for (int mt = 0; mt < 2; mt++) {
                ldsm4(afh[mt], bu + 0 * TILE_B + offA[mt][ks]);
                if (USE_AL) ldsm4(afl[mt], bu + 1 * TILE_B + offA[mt][ks]);
            }
#pragma unroll
            for (int nt = 0; nt < 2; nt++) {
                ldsm4(bfh[nt], bu + 2 * TILE_B + offB[nt][ks]);
                if (USE_BL) ldsm4(bfl[nt], bu + 3 * TILE_B + offB[nt][ks]);
            }
#pragma unroll
            for (int mt = 0; mt < 2; mt++)
#pragma unroll
                for (int nt = 0; nt < 2; nt++) {
                    mma_bf16(acc[mt][nt * 2 + 0], afh[mt], bfh[nt][0], bfh[nt][2]);
                    mma_bf16(acc[mt][nt * 2 + 1], afh[mt], bfh[nt][1], bfh[nt][3]);
                }
            if (USE_BL) {
#pragma unroll
                for (int mt = 0; mt < 2; mt++)
#pragma unroll
                    for (int nt = 0; nt < 2; nt++) {
                        mma_bf16(acc[mt][nt * 2 + 0], afh[mt], bfl[nt][0], bfl[nt][2]);
                        mma_bf16(acc[mt][nt * 2 + 1], afh[mt], bfl[nt][1], bfl[nt][3]);
                    }
            }
            if (USE_AL) {
#pragma unroll
                for (int mt = 0; mt < 2; mt++)
#pragma unroll
                    for (int nt = 0; nt < 2; nt++) {
                        mma_bf16(acc[mt][nt * 2 + 0], afl[mt], bfh[nt][0], bfh[nt][2]);
                        mma_bf16(acc[mt][nt * 2 + 1], afl[mt], bfh[nt][1], bfh[nt][3]);
                    }
            }
        }
        buf++;
        if (buf == NSTAGE) buf = 0;
    }
    __syncthreads();

    // ---- epilogue: accumulators -> staged smem [128][129] fp32 -> gmem ----
    float* st = (float*)sm;
    {
        int g = lane >> 2, t4 = lane & 3;
#pragma unroll
        for (int mt = 0; mt < 2; mt++) {
            int r = wm * 32 + mt * 16 + g;
#pragma unroll
            for (int j = 0; j < 4; j++) {
                int ccol = wn * 32 + j * 8 + 2 * t4;
                st[r * 129 + ccol]           = acc[mt][j][0];
                st[r * 129 + ccol + 1]       = acc[mt][j][1];
                st[(r + 8) * 129 + ccol]     = acc[mt][j][2];
                st[(r + 8) * 129 + ccol + 1] = acc[mt][j][3];
            }
        }
    }
    __syncthreads();

    if (EPI == EPI_BIAS_T_H) {
        // transposed h-only store + bias: dest [b][c][t]
#pragma unroll 4
        for (int it = 0; it < 8; it++) {
            int col = w + 16 * it;
            float bvv = bias[n0 + col];
#pragma unroll
            for (int j = 0; j < 4; j++) {
                int row = lane + 32 * j;
                float v = st[row * 129 + col] + bvv;
                size_t m = (size_t)m0 + row;
                int bb_ = (int)(m / TT);
                int t = (int)(m % TT);
                size_t off = ((size_t)bb_ * CC + (n0 + col)) * TT + t;
                Ch[off] = __float2bfloat16(v);
            }
        }
    } else if (EPI == EPI_F32_UW) {
#pragma unroll 2
        for (int rr = 0; rr < 8; rr++) {
            int row = w * 8 + rr;
            size_t m = (size_t)m0 + row;
            float um = uvec[(size_t)bz * TT + m];
#pragma unroll
            for (int cb = 0; cb < 4; cb++) {
                int col = lane + 32 * cb;
                float wn_ = wvec[(size_t)bz * TT + n0 + col];
                Cf[(size_t)bz * sC + m * ldc + n0 + col] = st[row * 129 + col] + um + wn_;
            }
        }
    } else {
        const float* resb = (EPI == EPI_F32_BIAS_RES) ? (res + (size_t)bz * sC) : nullptr;
        float bvv[4];
#pragma unroll
        for (int cb = 0; cb < 4; cb++)
            bvv[cb] = (EPI == EPI_F32_BIAS_RES) ? bias[n0 + lane + 32 * cb] : 0.f;

#pragma unroll 2
        for (int rr = 0; rr < 8; rr++) {
            int row = w * 8 + rr;
            size_t m = (size_t)m0 + row;
#pragma unroll
            for (int cb = 0; cb < 4; cb++) {
                int col = lane + 32 * cb;
                float v = st[row * 129 + col] + bvv[cb];
                size_t off = (size_t)bz * sC + m * ldc + n0 + col;
                if (EPI == EPI_F32) {
                    Cf[off] = v;
                } else if (EPI == EPI_F32_BIAS_RES) {
                    Cf[off] = v + resb[m * ldc + n0 + col];
                } else {  // EPI_SPLIT
                    bf16 h, l; split2(v, h, l);
                    Ch[off] = h;
                    Cl[off] = l;
                }
            }
        }
    }
}

// ------------------------------------------------------------------
// transpose + split: x[B,C,T] -> resid[B,T,C] (fp32 + hi/lo bf16)
// ------------------------------------------------------------------
__global__ __launch_bounds__(256)
void transpose_split(const float* __restrict__ x, float* __restrict__ r,
                     bf16* __restrict__ rh, bf16* __restrict__ rl) {
    __shared__ float tile[32][33];
    int b = blockIdx.z;
    int t0 = blockIdx.x * 32;
    int c0 = blockIdx.y * 32;
    const float* xb = x + (size_t)b * CC * TT;
    size_t ob = (size_t)b * TT * CC;
    int tx = threadIdx.x, ty = threadIdx.y;
#pragma unroll
    for (int i = ty; i < 32; i += 8)
        tile[i][tx] = xb[(size_t)(c0 + i) * TT + t0 + tx];
    __syncthreads();
#pragma unroll
    for (int i = ty; i < 32; i += 8) {
        float v = tile[tx][i];
        size_t off = ob + (size_t)(t0 + i) * CC + c0 + tx;
        r[off] = v;
        bf16 h, l; split2(v, h, l);
        rh[off] = h;
        rl[off] = l;
    }
}

// elementwise split W [512*512]
__global__ __launch_bounds__(256)
void splitW(const float* __restrict__ W, bf16* __restrict__ Th, bf16* __restrict__ Tl) {
    int i = blockIdx.x * 256 + threadIdx.x;
    float v = W[i];
    bf16 h, l; split2(v, h, l);
    Th[i] = h;
    Tl[i] = l;
}

// W [512,512] -> W^T hi/lo (used for Wo)
__global__ __launch_bounds__(256)
void wsplit(const float* __restrict__ W, bf16* __restrict__ Th, bf16* __restrict__ Tl) {
    __shared__ float tile[32][33];
    int k0 = blockIdx.y * 32, n0 = blockIdx.x * 32;
    int tx = threadIdx.x, ty = threadIdx.y;
#pragma unroll
    for (int i = ty; i < 32; i += 8)
        tile[i][tx] = W[(size_t)(k0 + i) * 512 + n0 + tx];
    __syncthreads();
#pragma unroll
    for (int i = ty; i < 32; i += 8) {
        float v = tile[tx][i];
        size_t off = (size_t)(n0 + i) * 512 + k0 + tx;
        bf16 h, l; split2(v, h, l);
        Th[off] = h;
        Tl[off] = l;
    }
}

// ---- small bias-path kernels ----
__global__ void dotk(const float* __restrict__ a, const float* __restrict__ b,
                     float* __restrict__ outscal) {
    int lane = threadIdx.x;
    float s = 0.f;
    for (int i = lane; i < 512; i += 32) s += a[i] * b[i];
#pragma unroll
    for (int o = 16; o; o >>= 1) s += __shfl_xor_sync(0xffffffffu, s, o);
    if (lane == 0) outscal[0] = s;
}

__global__ __launch_bounds__(256)
void matvec_row(const float* __restrict__ A, const float* __restrict__ v,
                float* __restrict__ out) {
    int c = blockIdx.x * 8 + (threadIdx.x >> 5);
    int lane = threadIdx.x & 31;
    float s = 0.f;
    for (int e = lane; e < 512; e += 32) s += A[(size_t)c * 512 + e] * v[e];
#pragma unroll
    for (int o = 16; o; o >>= 1) s += __shfl_xor_sync(0xffffffffu, s, o);
    if (lane == 0) out[c] = s;
}

__global__ __launch_bounds__(256)
void matvec_row_bf(const bf16* __restrict__ Th, const bf16* __restrict__ Tl,
                   const float* __restrict__ v, float* __restrict__ out) {
    int c = blockIdx.x * 8 + (threadIdx.x >> 5);
    int lane = threadIdx.x & 31;
    float s = 0.f;
    for (int e = lane; e < 512; e += 32) {
        float wv = __bfloat162float(Th[(size_t)c * 512 + e]) +
                   __bfloat162float(Tl[(size_t)c * 512 + e]);
        s += wv * v[e];
    }
#pragma unroll
    for (int o = 16; o; o >>= 1) s += __shfl_xor_sync(0xffffffffu, s, o);
    if (lane == 0) out[c] = s;
}

__global__ __launch_bounds__(256)
void rowdot(const float* __restrict__ r, const float* __restrict__ vv,
            const float* __restrict__ scal, float* __restrict__ u) {
    int row = blockIdx.x * 8 + (threadIdx.x >> 5);
    int lane = threadIdx.x & 31;
    float s = 0.f;
    for (int c = lane; c < 512; c += 32) s += r[(size_t)row * 512 + c] * vv[c];
#pragma unroll
    for (int o = 16; o; o >>= 1) s += __shfl_xor_sync(0xffffffffu, s, o);
    if (lane == 0) u[row] = s + scal[0];
}

// ------------------------------------------------------------------
// softmax (in-place fp32) + emit hi bf16
// ------------------------------------------------------------------
__global__ __launch_bounds__(256)
void softmax_split(float* __restrict__ attn, bf16* __restrict__ ah) {
    size_t ro = (size_t)blockIdx.x * TT;
    float* row = attn + ro;
    int t = threadIdx.x;
    float vals[8];
    float m = -1e30f;
#pragma unroll
    for (int j = 0; j < 8; j++) {
        vals[j] = row[t + 256 * j];
        m = fmaxf(m, vals[j]);
    }
#pragma unroll
    for (int o = 16; o; o >>= 1) m = fmaxf(m, __shfl_xor_sync(0xffffffffu, m, o));
    __shared__ float smax[8], ssum[8];
    if ((t & 31) == 0) smax[t >> 5] = m;
    __syncthreads();
    float rm = smax[0];
#pragma unroll
    for (int i = 1; i < 8; i++) rm = fmaxf(rm, smax[i]);

    float s = 0.f;
#pragma unroll
    for (int j = 0; j < 8; j++) {
        vals[j] = expf(vals[j] - rm);
        s += vals[j];
    }
#pragma unroll
    for (int o = 16; o; o >>= 1) s += __shfl_xor_sync(0xffffffffu, s, o);
    if ((t & 31) == 0) ssum[t >> 5] = s;
    __syncthreads();
    float tot = 0.f;
#pragma unroll
    for (int i = 0; i < 8; i++) tot += ssum[i];
    float inv = 1.f / tot;

#pragma unroll
    for (int j = 0; j < 8; j++) {
        float v = vals[j] * inv;
        row[t + 256 * j] = v;
        ah[ro + t + 256 * j] = __float2bfloat16(v);
    }
}

// ------------------------------------------------------------------
// LayerNorm over C=512
// ------------------------------------------------------------------
__global__ __launch_bounds__(128)
void ln_kernel(const float* __restrict__ h, const float* __restrict__ gamma,
               const float* __restrict__ beta, float* __restrict__ out) {
    const float* hr = h + (size_t)blockIdx.x * CC;
    int t = threadIdx.x;
    float4 v = ((const float4*)hr)[t];

    float s = v.x + v.y + v.z + v.w;
#pragma unroll
    for (int o = 16; o; o >>= 1) s += __shfl_xor_sync(0xffffffffu, s, o);
    __shared__ float s1[4], s2[4];
    if ((t & 31) == 0) s1[t >> 5] = s;
    __syncthreads();
    float mu = (s1[0] + s1[1] + s1[2] + s1[3]) * (1.f / CC);

    float dx = v.x - mu, dy = v.y - mu, dz = v.z - mu, dw = v.w - mu;
    float q = dx * dx + dy * dy + dz * dz + dw * dw;
#pragma unroll
    for (int o = 16; o; o >>= 1) q += __shfl_xor_sync(0xffffffffu, q, o);
    if ((t & 31) == 0) s2[t >> 5] = q;
    __syncthreads();
    float var = (s2[0] + s2[1] + s2[2] + s2[3]) * (1.f / CC);
    float inv = rsqrtf(var + LN_EPS);

    float4 g = ((const float4*)gamma)[t];
    float4 b = ((const float4*)beta)[t];
    float4 o4;
    o4.x = dx * inv * g.x + b.x;
    o4.y = dy * inv * g.y + b.y;
    o4.z = dz * inv * g.z + b.z;
    o4.w = dw * inv * g.w + b.w;
    ((float4*)(out + (size_t)blockIdx.x * CC))[t] = o4;
}

// ------------------------------------------------------------------
// launch
// ------------------------------------------------------------------
extern "C" void kernel_launch(void* const* d_in, const int* in_sizes, int n_in,
                              void* d_out, int out_size) {
    const float* x     = (const float*)d_in[0];
    const float* Wq    = (const float*)d_in[1];
    const float* bq    = (const float*)d_in[2];
    const float* Wk    = (const float*)d_in[3];
    const float* bk    = (const float*)d_in[4];
    const float* Wv    = (const float*)d_in[5];
    const float* bv    = (const float*)d_in[6];
    const float* Wo    = (const float*)d_in[7];
    const float* bo    = (const float*)d_in[8];
    const float* gamma = (const float*)d_in[9];
    const float* beta  = (const float*)d_in[10];

    float* out = (float*)d_out;
    float* attn = out;
    float* final_out = out + (size_t)BB * TT * TT;

    float *resid, *hbuf, *vqk, *vkq, *bvo, *uv, *wv_, *scal, *zero_s;
    bf16 *rh, *rl, *qmh, *qml, *vth, *anh;
    bf16 *wqh, *wql, *wkh, *wkl, *wvh, *wvl, *woh, *wol;
    bf16 *mth, *mtl, *nth, *ntl;
    cudaGetSymbolAddress((void**)&resid, g_resid);
    cudaGetSymbolAddress((void**)&hbuf, g_h);
    cudaGetSymbolAddress((void**)&rh, g_resid_h);
    cudaGetSymbolAddress((void**)&rl, g_resid_l);
    cudaGetSymbolAddress((void**)&qmh, g_qm_h);
    cudaGetSymbolAddress((void**)&qml, g_qm_l);
    cudaGetSymbolAddress((void**)&vth, g_vt_h);
    cudaGetSymbolAddress((void**)&anh, g_attn_h);
    cudaGetSymbolAddress((void**)&wqh, g_wq_h);
    cudaGetSymbolAddress((void**)&wql, g_wq_l);
    cudaGetSymbolAddress((void**)&wkh, g_wk_h);
    cudaGetSymbolAddress((void**)&wkl, g_wk_l);
    cudaGetSymbolAddress((void**)&wvh, g_wv_h);
    cudaGetSymbolAddress((void**)&wvl, g_wv_l);
    cudaGetSymbolAddress((void**)&woh, g_woT_h);
    cudaGetSymbolAddress((void**)&wol, g_woT_l);
    cudaGetSymbolAddress((void**)&mth, g_MT_h);
    cudaGetSymbolAddress((void**)&mtl, g_MT_l);
    cudaGetSymbolAddress((void**)&nth, g_NT_h);
    cudaGetSymbolAddress((void**)&ntl, g_NT_l);
    cudaGetSymbolAddress((void**)&vqk, g_vqk);
    cudaGetSymbolAddress((void**)&vkq, g_vkq);
    cudaGetSymbolAddress((void**)&bvo, g_bvo);
    cudaGetSymbolAddress((void**)&uv, g_u);
    cudaGetSymbolAddress((void**)&wv_, g_w);
    cudaGetSymbolAddress((void**)&scal, g_scal);
    cudaGetSymbolAddress((void**)&zero_s, g_zero_s);

    cudaFuncSetAttribute(hmma_gemm<EPI_SPLIT, 1, 1>,        cudaFuncAttributeMaxDynamicSharedMemorySize, GEMM_SMEM_REQ);
    cudaFuncSetAttribute(hmma_gemm<EPI_F32_UW, 1, 1>,       cudaFuncAttributeMaxDynamicSharedMemorySize, GEMM_SMEM_REQ);
    cudaFuncSetAttribute(hmma_gemm<EPI_BIAS_T_H, 0, 0>,     cudaFuncAttributeMaxDynamicSharedMemorySize, GEMM_SMEM_REQ);
    cudaFuncSetAttribute(hmma_gemm<EPI_F32_BIAS_RES, 0, 0>, cudaFuncAttributeMaxDynamicSharedMemorySize, GEMM_SMEM_REQ);

    // ---- prep: transpose + weight splits ----
    transpose_split<<<dim3(TT / 32, CC / 32, BB), dim3(32, 8)>>>(x, resid, rh, rl);
    splitW<<<1024, 256>>>(Wq, wqh, wql);
    splitW<<<1024, 256>>>(Wk, wkh, wkl);
    splitW<<<1024, 256>>>(Wv, wvh, wvl);
    wsplit<<<dim3(16, 16), dim3(32, 8)>>>(Wo, woh, wol);

    // bias-correction vectors (exact)
    dotk<<<1, 32>>>(bq, bk, scal);
    matvec_row<<<64, 256>>>(Wq, bk, vqk);
    matvec_row<<<64, 256>>>(Wk, bq, vkq);
    matvec_row_bf<<<64, 256>>>(woh, wol, bv, bvo);
    rowdot<<<(BB * TT) / 8, 256>>>(resid, vqk, scal, uv);     // u = r@vqk + bq.bk
    rowdot<<<(BB * TT) / 8, 256>>>(resid, vkq, zero_s, wv_);  // w = r@vkq

    // MT = Wk @ Wq^T, NT = Wo^T @ Wv^T — tiny 3-term GEMMs
    hmma_gemm<EPI_SPLIT, 1, 1><<<dim3(4, 4, 1), 512, GEMM_SMEM_REQ>>>(
        wkh, wkl, EE, 0, wqh, wql, EE, 0, nullptr, nullptr, nullptr, nullptr,
        nullptr, mth, mtl, CC, 0, EE);
    hmma_gemm<EPI_SPLIT, 1, 1><<<dim3(4, 4, 1), 512, GEMM_SMEM_REQ>>>(
        woh, wol, EE, 0, wvh, wvl, EE, 0, nullptr, nullptr, nullptr, nullptr,
        nullptr, nth, ntl, CC, 0, EE);

    // qm = resid @ M   (3-term, split out)
    hmma_gemm<EPI_SPLIT, 1, 1><<<dim3(CC / 128, (BB * TT) / 128, 1), 512, GEMM_SMEM_REQ>>>(
        rh, rl, CC, 0, mth, mtl, CC, 0, nullptr, nullptr, nullptr, nullptr,
        nullptr, qmh, qml, CC, 0, CC);

    // energy = qm @ resid^T + u[t] + w[s]  (3-term) -> fp32 logits in attn region
    hmma_gemm<EPI_F32_UW, 1, 1><<<dim3(TT / 128, TT / 128, BB), 512, GEMM_SMEM_REQ>>>(
        qmh, qml, CC, (size_t)TT * CC, rh, rl, CC, (size_t)TT * CC,
        nullptr, nullptr, uv, wv_,
        attn, nullptr, nullptr, TT, (size_t)TT * TT, CC);

    // softmax in-place + emit hi bf16
    softmax_split<<<BB * TT, 256>>>(attn, anh);

    // vw = resid @ N + bvo   (1-term; transposed h-only out -> [B][C][T])
    hmma_gemm<EPI_BIAS_T_H, 0, 0><<<dim3(CC / 128, (BB * TT) / 128, 1), 512, GEMM_SMEM_REQ>>>(
        rh, nullptr, CC, 0, nth, nullptr, CC, 0, bvo, nullptr, nullptr, nullptr,
        nullptr, vth, nullptr, CC, 0, CC);

    // h = attn_h @ vw^T + bo + resid   (1-term)
    hmma_gemm<EPI_F32_BIAS_RES, 0, 0><<<dim3(CC / 128, TT / 128, BB), 512, GEMM_SMEM_REQ>>>(
        anh, nullptr, TT, (size_t)TT * TT, vth, nullptr, TT, (size_t)CC * TT,
        bo, resid, nullptr, nullptr,
        hbuf, nullptr, nullptr, CC, (size_t)TT * CC, TT);

    // LayerNorm -> final output region
    ln_kernel<<<BB * TT, 128>>>(hbuf, gamma, beta, final_out);
}

// round 13
// speedup vs baseline: 1.4878x; 1.0456x over previous
#include <cuda_runtime.h>
#include <cuda_bf16.h>
#include <cstdint>

#define BB 8
#define CC 512
#define TT 2048
#define EE 512
#define LN_EPS 1e-5f

typedef __nv_bfloat16 bf16;

// ------------------------------------------------------------------
// scratch (device globals — allocation-free rule)
// ------------------------------------------------------------------
__device__ bf16  g_resid_h[BB * TT * CC];
__device__ bf16  g_resid_l[BB * TT * CC];
__device__ bf16  g_qm_h[BB * TT * CC];
__device__ bf16  g_qm_l[BB * TT * CC];
__device__ bf16  g_vt_h[BB * CC * TT];     // vw transposed: [B][C][T]
__device__ bf16  g_attn_h[(size_t)BB * TT * TT];
__device__ float g_h[BB * TT * CC];
__device__ bf16  g_wq_h[CC * EE], g_wq_l[CC * EE];
__device__ bf16  g_wk_h[CC * EE], g_wk_l[CC * EE];
__device__ bf16  g_wv_h[CC * EE], g_wv_l[CC * EE];
__device__ bf16  g_woT_h[CC * EE], g_woT_l[CC * EE];
__device__ bf16  g_MT_h[CC * CC], g_MT_l[CC * CC];     // MT = Wk @ Wq^T
__device__ bf16  g_NT_h[CC * CC], g_NT_l[CC * CC];     // NT = Wo^T @ Wv^T
__device__ float g_vqk[CC];
__device__ float g_vkq[CC];
__device__ float g_bvo[CC];
__device__ float g_u[BB * TT];
__device__ float g_w[BB * TT];
__device__ float g_scal[1];

// ------------------------------------------------------------------
// low-level helpers
// ------------------------------------------------------------------
__device__ __forceinline__ uint32_t smem_u32(const void* p) {
    uint32_t a;
    asm("{ .reg .u64 t; cvta.to.shared.u64 t, %1; cvt.u32.u64 %0, t; }" : "=r"(a) : "l"(p));
    return a;
}
__device__ __forceinline__ uint32_t swz64(uint32_t o) { return o ^ ((o >> 3) & 0x30); }

#define CP16(dst, src) \
    asm volatile("cp.async.cg.shared.global [%0], [%1], 16;" :: "r"(dst), "l"(src))
#define CP_COMMIT() asm volatile("cp.async.commit_group;" ::: "memory")
#define CP_WAIT(n)  asm volatile("cp.async.wait_group %0;" :: "n"(n) : "memory")

__device__ __forceinline__ void ldsm4(uint32_t* r, uint32_t addr) {
    asm volatile("ldmatrix.sync.aligned.m8n8.x4.shared.b16 {%0,%1,%2,%3}, [%4];"
                 : "=r"(r[0]), "=r"(r[1]), "=r"(r[2]), "=r"(r[3]) : "r"(addr));
}

__device__ __forceinline__ void mma_bf16(float* c, const uint32_t* a,
                                         uint32_t b0, uint32_t b1) {
    asm("mma.sync.aligned.m16n8k16.row.col.f32.bf16.bf16.f32 "
        "{%0,%1,%2,%3}, {%4,%5,%6,%7}, {%8,%9}, {%0,%1,%2,%3};"
        : "+f"(c[0]), "+f"(c[1]), "+f"(c[2]), "+f"(c[3])
        : "r"(a[0]), "r"(a[1]), "r"(a[2]), "r"(a[3]), "r"(b0), "r"(b1));
}

__device__ __forceinline__ void split2(float v, bf16& h, bf16& l) {
    h = __float2bfloat16(v);
    l = __float2bfloat16(v - __bfloat162float(h));
}

// ------------------------------------------------------------------
// HMMA GEMM, templated N-tile (BN = 128 or 64). M tile fixed 128, BK=32.
// D = selected terms of (Ah+Al)·(Bh+Bl)^T; 512 threads, warps 4m x 4n.
// ------------------------------------------------------------------
enum { EPI_F32_UW = 0, EPI_SPLIT = 1, EPI_BIAS_T_H = 2, EPI_F32_BIAS_RES = 3 };

template <int EPI, int USE_AL, int USE_BL, int BN>
__global__ __launch_bounds__(512)
void hmma_gemm(const bf16* __restrict__ Ah, const bf16* __restrict__ Al, int ldA, size_t sA,
               const bf16* __restrict__ Bh, const bf16* __restrict__ Bl, int ldB, size_t sB,
               const float* __restrict__ bias,
               const bf16* __restrict__ resh, const bf16* __restrict__ resl,
               const float* __restrict__ uvec, const float* __restrict__ wvec,
               float* __restrict__ Cf, bf16* __restrict__ Ch, bf16* __restrict__ Cl,
               int ldc, size_t sC, int K) {
    constexpr int TBB = BN * 64;               // bytes per B tile
    constexpr int CHUNK = 16384 + 2 * TBB;     // Ah(8K) Al(8K) Bh Bl
    constexpr int NT = BN / 64;                // B nt-tiles per warp
    constexpr int JN = BN / 32;                // 8-col groups per warp
    constexpr int P = BN + 1;                  // epilogue stage pitch

    extern __shared__ char sm[];
    uint32_t smu = smem_u32(sm);

    const int tid = threadIdx.x;
    const int w = tid >> 5, lane = tid & 31;
    const int bz = blockIdx.z;
    const int m0 = blockIdx.y * 128;
    const int n0 = blockIdx.x * BN;

    const bf16* pAh = Ah + (size_t)bz * sA + (size_t)m0 * ldA;
    const bf16* pAl = USE_AL ? (Al + (size_t)bz * sA + (size_t)m0 * ldA) : nullptr;
    const bf16* pBh = Bh + (size_t)bz * sB + (size_t)n0 * ldB;
    const bf16* pBl = USE_BL ? (Bl + (size_t)bz * sB + (size_t)n0 * ldB) : nullptr;

    const int lrow = tid >> 2, lcs = tid & 3;
    const uint32_t loff = swz64((uint32_t)(lrow * 64 + lcs * 16));
    const bool bload = (BN == 128) || (tid < BN * 4);
    auto load_chunk = [&](int buf, int k0) {
        uint32_t base = smu + (uint32_t)buf * CHUNK;
        CP16(base + loff, pAh + (size_t)lrow * ldA + k0 + lcs * 8);
        if (USE_AL) CP16(base + 8192 + loff, pAl + (size_t)lrow * ldA + k0 + lcs * 8);
        if (bload) {
            CP16(base + 16384 + loff, pBh + (size_t)lrow * ldB + k0 + lcs * 8);
            if (USE_BL) CP16(base + 16384 + TBB + loff, pBl + (size_t)lrow * ldB + k0 + lcs * 8);
        }
    };

    const int wm = w >> 2, wn = w & 3;
    const int lr = lane & 7;
    const int r8 = (lane >> 3) & 1;
    const int chi = lane >> 4;

    uint32_t offA[2][2], offB[NT][2];
#pragma unroll
    for (int mt = 0; mt < 2; mt++)
#pragma unroll
        for (int ks = 0; ks < 2; ks++)
            offA[mt][ks] = swz64((uint32_t)((wm * 32 + mt * 16 + r8 * 8 + lr) * 64 + (2 * ks + chi) * 16));
#pragma unroll
    for (int nt = 0; nt < NT; nt++)
#pragma unroll
        for (int ks = 0; ks < 2; ks++)
            offB[nt][ks] = swz64((uint32_t)((wn * (BN / 4) + nt * 16 + r8 * 8 + lr) * 64 + (2 * ks + chi) * 16));

    float acc[2][JN][4];
#pragma unroll
    for (int i = 0; i < 2; i++)
#pragma unroll
        for (int j = 0; j < JN; j++)
#pragma unroll
            for (int q = 0; q < 4; q++) acc[i][j][q] = 0.f;

    const int nch = K / 32;
    load_chunk(0, 0);
    CP_COMMIT();
    if (nch > 1) load_chunk(1, 32);
    CP_COMMIT();

    int buf = 0;
    for (int c = 0; c < nch; c++) {
        CP_WAIT(1);
        __syncthreads();

        if (c + 2 < nch) {
            int fb = buf + 2;
            if (fb >= 3) fb -= 3;
            load_chunk(fb, (c + 2) * 32);
        }
        CP_COMMIT();

        uint32_t bu = smu + (uint32_t)buf * CHUNK;
#pragma unroll
        for (int ks = 0; ks < 2; ks++) {
            uint32_t afh[2][4], afl[2][4], bfh[NT][4], bfl[NT][4];
#pragma unroll
            for (int mt = 0; mt < 2; mt++) {
                ldsm4(afh[mt], bu + offA[mt][ks]);
                if (USE_AL) ldsm4(afl[mt], bu + 8192 + offA[mt][ks]);
            }
#pragma unroll
            for (int nt = 0; nt < NT; nt++) {
                ldsm4(bfh[nt], bu + 16384 + offB[nt][ks]);
                if (USE_BL) ldsm4(bfl[nt], bu + 16384 + TBB + offB[nt][ks]);
            }
#pragma unroll
            for (int mt = 0; mt < 2; mt++)
#pragma unroll
                for (int nt = 0; nt < NT; nt++) {
                    mma_bf16(acc[mt][nt * 2 + 0], afh[mt], bfh[nt][0], bfh[nt][2]);
                    mma_bf16(acc[mt][nt * 2 + 1], afh[mt], bfh[nt][1], bfh[nt][3]);
                }
            if (USE_BL) {
#pragma unroll
                for (int mt = 0; mt < 2; mt++)
#pragma unroll
                    for (int nt = 0; nt < NT; nt++) {
                        mma_bf16(acc[mt][nt * 2 + 0], afh[mt], bfl[nt][0], bfl[nt][2]);
                        mma_bf16(acc[mt][nt * 2 + 1], afh[mt], bfl[nt][1], bfl[nt][3]);
                    }
            }
            if (USE_AL) {
#pragma unroll
                for (int mt = 0; mt < 2; mt++)
#pragma unroll
                    for (int nt = 0; nt < NT; nt++) {
                        mma_bf16(acc[mt][nt * 2 + 0], afl[mt], bfh[nt][0], bfh[nt][2]);
                        mma_bf16(acc[mt][nt * 2 + 1], afl[mt], bfh[nt][1], bfh[nt][3]);
                    }
            }
        }
        buf++;
        if (buf == 3) buf = 0;
    }
    __syncthreads();

    // ---- epilogue: accumulators -> staged smem [128][P] fp32 -> gmem ----
    float* st = (float*)sm;
    {
        int g = lane >> 2, t4 = lane & 3;
#pragma unroll
        for (int mt = 0; mt < 2; mt++) {
            int r = wm * 32 + mt * 16 + g;
#pragma unroll
            for (int j = 0; j < JN; j++) {
                int ccol = wn * (BN / 4) + j * 8 + 2 * t4;
                st[r * P + ccol]           = acc[mt][j][0];
                st[r * P + ccol + 1]       = acc[mt][j][1];
                st[(r + 8) * P + ccol]     = acc[mt][j][2];
                st[(r + 8) * P + ccol + 1] = acc[mt][j][3];
            }
        }
    }
    __syncthreads();

    if (EPI == EPI_BIAS_T_H) {
        // transposed h-only store + bias: dest [b][c][t]
#pragma unroll
        for (int it = 0; it < BN / 16; it++) {
            int col = w + 16 * it;
            float bvv = bias[n0 + col];
#pragma unroll
            for (int j = 0; j < 4; j++) {
                int row = lane + 32 * j;
                float v = st[row * P + col] + bvv;
                size_t m = (size_t)m0 + row;
                int bb_ = (int)(m / TT);
                int t = (int)(m % TT);
                Ch[((size_t)bb_ * CC + (n0 + col)) * TT + t] = __float2bfloat16(v);
            }
        }
    } else if (EPI == EPI_F32_UW) {
#pragma unroll
        for (int rr = 0; rr < 8; rr++) {
            int row = w * 8 + rr;
            size_t m = (size_t)m0 + row;
            float um = uvec[(size_t)bz * TT + m];
#pragma unroll
            for (int cb = 0; cb < BN / 32; cb++) {
                int col = lane + 32 * cb;
                float wn_ = wvec[(size_t)bz * TT + n0 + col];
                Cf[(size_t)bz * sC + m * ldc + n0 + col] = st[row * P + col] + um + wn_;
            }
        }
    } else {
#pragma unroll
        for (int rr = 0; rr < 8; rr++) {
            int row = w * 8 + rr;
            size_t m = (size_t)m0 + row;
#pragma unroll
            for (int cb = 0; cb < BN / 32; cb++) {
                int col = lane + 32 * cb;
                float v = st[row * P + col];
                size_t off = (size_t)bz * sC + m * ldc + n0 + col;
                if (EPI == EPI_F32_BIAS_RES) {
                    float r = __bfloat162float(resh[off]) + __bfloat162float(resl[off]);
                    Cf[off] = v + bias[n0 + col] + r;
                } else {  // EPI_SPLIT
                    bf16 h, l; split2(v, h, l);
                    Ch[off] = h;
                    Cl[off] = l;
                }
            }
        }
    }
}

// ------------------------------------------------------------------
// transpose + split + fused u/w rowdots:
// x[B,C,T] -> rh/rl [B,T,C]; u += r@vqk (+scal via zero-init path), w += r@vkq
// ------------------------------------------------------------------
__global__ __launch_bounds__(256)
void transpose_split_fused(const float* __restrict__ x,
                           bf16* __restrict__ rh, bf16* __restrict__ rl,
                           const float* __restrict__ vqk, const float* __restrict__ vkq,
                           float* __restrict__ u, float* __restrict__ wv) {
    __shared__ float tile[32][33];
    int b = blockIdx.z;
    int t0 = blockIdx.x * 32;
    int c0 = blockIdx.y * 32;
    const float* xb = x + (size_t)b * CC * TT;
    size_t ob = (size_t)b * TT * CC;
    int tx = threadIdx.x, ty = threadIdx.y;
#pragma unroll
    for (int i = ty; i < 32; i += 8)
        tile[i][tx] = xb[(size_t)(c0 + i) * TT + t0 + tx];
    __syncthreads();
    float vq = vqk[c0 + tx], vk = vkq[c0 + tx];
#pragma unroll
    for (int i = ty; i < 32; i += 8) {
        float v = tile[tx][i];
        size_t off = ob + (size_t)(t0 + i) * CC + c0 + tx;
        bf16 h, l; split2(v, h, l);
        rh[off] = h;
        rl[off] = l;
        // fused row-dots (warp lanes span the 32 channels of this tile)
        float su = v * vq, sw = v * vk;
#pragma unroll
        for (int o = 16; o; o >>= 1) {
            su += __shfl_xor_sync(0xffffffffu, su, o);
            sw += __shfl_xor_sync(0xffffffffu, sw, o);
        }
        if (tx == 0) {
            atomicAdd(&u[(size_t)b * TT + t0 + i], su);
            atomicAdd(&wv[(size_t)b * TT + t0 + i], sw);
        }
    }
}

// zero u/w and seed u with scal (bq.bk) — must run every launch (graph replays)
__global__ __launch_bounds__(256)
void zero_uw(float* __restrict__ u, float* __restrict__ wv, const float* __restrict__ scal) {
    int i = blockIdx.x * 256 + threadIdx.x;
    u[i] = scal[0];
    wv[i] = 0.f;
}

// merged elementwise split of Wq, Wk, Wv
__global__ __launch_bounds__(256)
void splitW3(const float* __restrict__ Wq, const float* __restrict__ Wk,
             const float* __restrict__ Wv,
             bf16* __restrict__ qh, bf16* __restrict__ ql,
             bf16* __restrict__ kh, bf16* __restrict__ kl,
             bf16* __restrict__ vh, bf16* __restrict__ vl) {
    int i = blockIdx.x * 256 + threadIdx.x;
    bf16 h, l;
    split2(Wq[i], h, l); qh[i] = h; ql[i] = l;
    split2(Wk[i], h, l); kh[i] = h; kl[i] = l;
    split2(Wv[i], h, l); vh[i] = h; vl[i] = l;
}

// W [512,512] -> W^T hi/lo (Wo)
__global__ __launch_bounds__(256)
void wsplit(const float* __restrict__ W, bf16* __restrict__ Th, bf16* __restrict__ Tl) {
    __shared__ float tile[32][33];
    int k0 = blockIdx.y * 32, n0 = blockIdx.x * 32;
    int tx = threadIdx.x, ty = threadIdx.y;
#pragma unroll
    for (int i = ty; i < 32; i += 8)
        tile[i][tx] = W[(size_t)(k0 + i) * 512 + n0 + tx];
    __syncthreads();
#pragma unroll
    for (int i = ty; i < 32; i += 8) {
        float v = tile[tx][i];
        size_t off = (size_t)(n0 + i) * 512 + k0 + tx;
        bf16 h, l; split2(v, h, l);
        Th[off] = h;
        Tl[off] = l;
    }
}

// ---- small bias-path kernels ----
__global__ void dotk(const float* __restrict__ a, const float* __restrict__ b,
                     float* __restrict__ outscal) {
    int lane = threadIdx.x;
    float s = 0.f;
    for (int i = lane; i < 512; i += 32) s += a[i] * b[i];
#pragma unroll
    for (int o = 16; o; o >>= 1) s += __shfl_xor_sync(0xffffffffu, s, o);
    if (lane == 0) outscal[0] = s;
}

// vqk[c] = Wq[c,:]@bk ; vkq[c] = Wk[c,:]@bq  (merged)
__global__ __launch_bounds__(256)
void matvec2(const float* __restrict__ Wq, const float* __restrict__ bk,
             const float* __restrict__ Wk, const float* __restrict__ bq,
             float* __restrict__ vqk, float* __restrict__ vkq) {
    int c = blockIdx.x * 8 + (threadIdx.x >> 5);
    int lane = threadIdx.x & 31;
    float s1 = 0.f, s2 = 0.f;
    for (int e = lane; e < 512; e += 32) {
        s1 += Wq[(size_t)c * 512 + e] * bk[e];
        s2 += Wk[(size_t)c * 512 + e] * bq[e];
    }
#pragma unroll
    for (int o = 16; o; o >>= 1) {
        s1 += __shfl_xor_sync(0xffffffffu, s1, o);
        s2 += __shfl_xor_sync(0xffffffffu, s2, o);
    }
    if (lane == 0) { vqk[c] = s1; vkq[c] = s2; }
}

// bvo[c] = (WoT_h+WoT_l)[c,:]@bv
__global__ __launch_bounds__(256)
void matvec_row_bf(const bf16* __restrict__ Th, const bf16* __restrict__ Tl,
                   const float* __restrict__ v, float* __restrict__ out) {
    int c = blockIdx.x * 8 + (threadIdx.x >> 5);
    int lane = threadIdx.x & 31;
    float s = 0.f;
    for (int e = lane; e < 512; e += 32) {
        float wv = __bfloat162float(Th[(size_t)c * 512 + e]) +
                   __bfloat162float(Tl[(size_t)c * 512 + e]);
        s += wv * v[e];
    }
#pragma unroll
    for (int o = 16; o; o >>= 1) s += __shfl_xor_sync(0xffffffffu, s, o);
    if (lane == 0) out[c] = s;
}

// ------------------------------------------------------------------
// softmax (in-place fp32) + emit hi bf16
// ------------------------------------------------------------------
__global__ __launch_bounds__(256)
void softmax_split(float* __restrict__ attn, bf16* __restrict__ ah) {
    size_t ro = (size_t)blockIdx.x * TT;
    float* row = attn + ro;
    int t = threadIdx.x;
    float vals[8];
    float m = -1e30f;
#pragma unroll
    for (int j = 0; j < 8; j++) {
        vals[j] = row[t + 256 * j];
        m = fmaxf(m, vals[j]);
    }
#pragma unroll
    for (int o = 16; o; o >>= 1) m = fmaxf(m, __shfl_xor_sync(0xffffffffu, m, o));
    __shared__ float smax[8], ssum[8];
    if ((t & 31) == 0) smax[t >> 5] = m;
    __syncthreads();
    float rm = smax[0];
#pragma unroll
    for (int i = 1; i < 8; i++) rm = fmaxf(rm, smax[i]);

    float s = 0.f;
#pragma unroll
    for (int j = 0; j < 8; j++) {
        vals[j] = expf(vals[j] - rm);
        s += vals[j];
    }
#pragma unroll
    for (int o = 16; o; o >>= 1) s += __shfl_xor_sync(0xffffffffu, s, o);
    if ((t & 31) == 0) ssum[t >> 5] = s;
    __syncthreads();
    float tot = 0.f;
#pragma unroll
    for (int i = 0; i < 8; i++) tot += ssum[i];
    float inv = 1.f / tot;

#pragma unroll
    for (int j = 0; j < 8; j++) {
        float v = vals[j] * inv;
        row[t + 256 * j] = v;
        ah[ro + t + 256 * j] = __float2bfloat16(v);
    }
}

// ------------------------------------------------------------------
// LayerNorm over C=512
// ------------------------------------------------------------------
__global__ __launch_bounds__(128)
void ln_kernel(const float* __restrict__ h, const float* __restrict__ gamma,
               const float* __restrict__ beta, float* __restrict__ out) {
    const float* hr = h + (size_t)blockIdx.x * CC;
    int t = threadIdx.x;
    float4 v = ((const float4*)hr)[t];

    float s = v.x + v.y + v.z + v.w;
#pragma unroll
    for (int o = 16; o; o >>= 1) s += __shfl_xor_sync(0xffffffffu, s, o);
    __shared__ float s1[4], s2[4];
    if ((t & 31) == 0) s1[t >> 5] = s;
    __syncthreads();
    float mu = (s1[0] + s1[1] + s1[2] + s1[3]) * (1.f / CC);

    float dx = v.x - mu, dy = v.y - mu, dz = v.z - mu, dw = v.w - mu;
    float q = dx * dx + dy * dy + dz * dz + dw * dw;
#pragma unroll
    for (int o = 16; o; o >>= 1) q += __shfl_xor_sync(0xffffffffu, q, o);
    if ((t & 31) == 0) s2[t >> 5] = q;
    __syncthreads();
    float var = (s2[0] + s2[1] + s2[2] + s2[3]) * (1.f / CC);
    float inv = rsqrtf(var + LN_EPS);

    float4 g = ((const float4*)gamma)[t];
    float4 b = ((const float4*)beta)[t];
    float4 o4;
    o4.x = dx * inv * g.x + b.x;
    o4.y = dy * inv * g.y + b.y;
    o4.z = dz * inv * g.z + b.z;
    o4.w = dw * inv * g.w + b.w;
    ((float4*)(out + (size_t)blockIdx.x * CC))[t] = o4;
}

// ------------------------------------------------------------------
// launch
// ------------------------------------------------------------------
#define SMEM128 (3 * (16384 + 2 * 8192))   // 98304
#define SMEM64  (3 * (16384 + 2 * 4096))   // 73728

extern "C" void kernel_launch(void* const* d_in, const int* in_sizes, int n_in,
                              void* d_out, int out_size) {
    const float* x     = (const float*)d_in[0];
    const float* Wq    = (const float*)d_in[1];
    const float* bq    = (const float*)d_in[2];
    const float* Wk    = (const float*)d_in[3];
    const float* bk    = (const float*)d_in[4];
    const float* Wv    = (const float*)d_in[5];
    const float* bv    = (const float*)d_in[6];
    const float* Wo    = (const float*)d_in[7];
    const float* bo    = (const float*)d_in[8];
    const float* gamma = (const float*)d_in[9];
    const float* beta  = (const float*)d_in[10];

    float* out = (float*)d_out;
    float* attn = out;
    float* final_out = out + (size_t)BB * TT * TT;

    float *hbuf, *vqk, *vkq, *bvo, *uv, *wv_, *scal;
    bf16 *rh, *rl, *qmh, *qml, *vth, *anh;
    bf16 *wqh, *wql, *wkh, *wkl, *wvh, *wvl, *woh, *wol;
    bf16 *mth, *mtl, *nth, *ntl;
    cudaGetSymbolAddress((void**)&hbuf, g_h);
    cudaGetSymbolAddress((void**)&rh, g_resid_h);
    cudaGetSymbolAddress((void**)&rl, g_resid_l);
    cudaGetSymbolAddress((void**)&qmh, g_qm_h);
    cudaGetSymbolAddress((void**)&qml, g_qm_l);
    cudaGetSymbolAddress((void**)&vth, g_vt_h);
    cudaGetSymbolAddress((void**)&anh, g_attn_h);
    cudaGetSymbolAddress((void**)&wqh, g_wq_h);
    cudaGetSymbolAddress((void**)&wql, g_wq_l);
    cudaGetSymbolAddress((void**)&wkh, g_wk_h);
    cudaGetSymbolAddress((void**)&wkl, g_wk_l);
    cudaGetSymbolAddress((void**)&wvh, g_wv_h);
    cudaGetSymbolAddress((void**)&wvl, g_wv_l);
    cudaGetSymbolAddress((void**)&woh, g_woT_h);
    cudaGetSymbolAddress((void**)&wol, g_woT_l);
    cudaGetSymbolAddress((void**)&mth, g_MT_h);
    cudaGetSymbolAddress((void**)&mtl, g_MT_l);
    cudaGetSymbolAddress((void**)&nth, g_NT_h);
    cudaGetSymbolAddress((void**)&ntl, g_NT_l);
    cudaGetSymbolAddress((void**)&vqk, g_vqk);
    cudaGetSymbolAddress((void**)&vkq, g_vkq);
    cudaGetSymbolAddress((void**)&bvo, g_bvo);
    cudaGetSymbolAddress((void**)&uv, g_u);
    cudaGetSymbolAddress((void**)&wv_, g_w);
    cudaGetSymbolAddress((void**)&scal, g_scal);

    cudaFuncSetAttribute(hmma_gemm<EPI_SPLIT, 1, 1, 128>,       cudaFuncAttributeMaxDynamicSharedMemorySize, SMEM128);
    cudaFuncSetAttribute(hmma_gemm<EPI_SPLIT, 1, 1, 64>,        cudaFuncAttributeMaxDynamicSharedMemorySize, SMEM64);
    cudaFuncSetAttribute(hmma_gemm<EPI_F32_UW, 1, 1, 128>,      cudaFuncAttributeMaxDynamicSharedMemorySize, SMEM128);
    cudaFuncSetAttribute(hmma_gemm<EPI_BIAS_T_H, 0, 0, 64>,     cudaFuncAttributeMaxDynamicSharedMemorySize, SMEM64);
    cudaFuncSetAttribute(hmma_gemm<EPI_F32_BIAS_RES, 0, 0, 64>, cudaFuncAttributeMaxDynamicSharedMemorySize, SMEM64);

    // ---- prep: bias vectors first (transpose consumes vqk/vkq) ----
    dotk<<<1, 32>>>(bq, bk, scal);
    zero_uw<<<(BB * TT) / 256, 256>>>(uv, wv_, scal);   // u seeded with bq.bk
    matvec2<<<64, 256>>>(Wq, bk, Wk, bq, vqk, vkq);

    // transpose + split + fused u/w rowdots
    transpose_split_fused<<<dim3(TT / 32, CC / 32, BB), dim3(32, 8)>>>(
        x, rh, rl, vqk, vkq, uv, wv_);

    // weight splits
    splitW3<<<1024, 256>>>(Wq, Wk, Wv, wqh, wql, wkh, wkl, wvh, wvl);
    wsplit<<<dim3(16, 16), dim3(32, 8)>>>(Wo, woh, wol);
    matvec_row_bf<<<64, 256>>>(woh, wol, bv, bvo);

    // MT = Wk @ Wq^T, NT = Wo^T @ Wv^T — tiny 3-term GEMMs
    hmma_gemm<EPI_SPLIT, 1, 1, 128><<<dim3(4, 4, 1), 512, SMEM128>>>(
        wkh, wkl, EE, 0, wqh, wql, EE, 0, nullptr, nullptr, nullptr, nullptr, nullptr,
        nullptr, mth, mtl, CC, 0, EE);
    hmma_gemm<EPI_SPLIT, 1, 1, 128><<<dim3(4, 4, 1), 512, SMEM128>>>(
        woh, wol, EE, 0, wvh, wvl, EE, 0, nullptr, nullptr, nullptr, nullptr, nullptr,
        nullptr, nth, ntl, CC, 0, EE);

    // qm = resid @ M  (3-term, BN=64 -> 1024 CTAs)
    hmma_gemm<EPI_SPLIT, 1, 1, 64><<<dim3(CC / 64, (BB * TT) / 128, 1), 512, SMEM64>>>(
        rh, rl, CC, 0, mth, mtl, CC, 0, nullptr, nullptr, nullptr, nullptr, nullptr,
        nullptr, qmh, qml, CC, 0, CC);

    // energy = qm @ resid^T + u[t] + w[s]  (3-term, BN=128)
    hmma_gemm<EPI_F32_UW, 1, 1, 128><<<dim3(TT / 128, TT / 128, BB), 512, SMEM128>>>(
        qmh, qml, CC, (size_t)TT * CC, rh, rl, CC, (size_t)TT * CC,
        nullptr, nullptr, nullptr, uv, wv_,
        attn, nullptr, nullptr, TT, (size_t)TT * TT, CC);

    // softmax in-place + emit hi bf16
    softmax_split<<<BB * TT, 256>>>(attn, anh);

    // vw = resid @ N + bvo  (1-term, BN=64, transposed h-only out)
    hmma_gemm<EPI_BIAS_T_H, 0, 0, 64><<<dim3(CC / 64, (BB * TT) / 128, 1), 512, SMEM64>>>(
        rh, nullptr, CC, 0, nth, nullptr, CC, 0, bvo, nullptr, nullptr, nullptr, nullptr,
        nullptr, vth, nullptr, CC, 0, CC);

    // h = attn_h @ vw^T + bo + (rh+rl)  (1-term, BN=64)
    hmma_gemm<EPI_F32_BIAS_RES, 0, 0, 64><<<dim3(CC / 64, TT / 128, BB), 512, SMEM64>>>(
        anh, nullptr, TT, (size_t)TT * TT, vth, nullptr, TT, (size_t)CC * TT,
        bo, rh, rl, nullptr, nullptr,
        hbuf, nullptr, nullptr, CC, (size_t)TT * CC, TT);

    // LayerNorm -> final output region
    ln_kernel<<<BB * TT, 128>>>(hbuf, gamma, beta, final_out);
}

// round 14
// speedup vs baseline: 1.6665x; 1.1201x over previous
#include <cuda_runtime.h>
#include <cuda_bf16.h>
#include <cstdint>

#define BB 8
#define CC 512
#define TT 2048
#define EE 512
#define LN_EPS 1e-5f

typedef __nv_bfloat16 bf16;

// ------------------------------------------------------------------
// scratch (device globals — allocation-free rule)
// ------------------------------------------------------------------
__device__ bf16  g_resid_h[BB * TT * CC];
__device__ bf16  g_resid_l[BB * TT * CC];
__device__ bf16  g_qm_h[BB * TT * CC];
__device__ bf16  g_qm_l[BB * TT * CC];
__device__ bf16  g_vt_h[BB * CC * TT];     // vw transposed: [B][C][T]
__device__ bf16  g_attn_h[(size_t)BB * TT * TT];
__device__ float g_h[BB * TT * CC];
__device__ bf16  g_wq_h[CC * EE], g_wq_l[CC * EE];
__device__ bf16  g_wk_h[CC * EE], g_wk_l[CC * EE];
__device__ bf16  g_wv_h[CC * EE], g_wv_l[CC * EE];
__device__ bf16  g_woT_h[CC * EE], g_woT_l[CC * EE];
__device__ bf16  g_MT_h[CC * CC], g_MT_l[CC * CC];     // MT = Wk @ Wq^T
__device__ bf16  g_NT_h[CC * CC], g_NT_l[CC * CC];     // NT = Wo^T @ Wv^T
__device__ float g_vqk[CC];
__device__ float g_vkq[CC];
__device__ float g_bvo[CC];
__device__ float g_u[BB * TT];
__device__ float g_w[BB * TT];
__device__ float g_scal[1];

// ------------------------------------------------------------------
// low-level helpers
// ------------------------------------------------------------------
__device__ __forceinline__ uint32_t smem_u32(const void* p) {
    uint32_t a;
    asm("{ .reg .u64 t; cvta.to.shared.u64 t, %1; cvt.u32.u64 %0, t; }" : "=r"(a) : "l"(p));
    return a;
}
__device__ __forceinline__ uint32_t swz64(uint32_t o) { return o ^ ((o >> 3) & 0x30); }

#define CP16(dst, src) \
    asm volatile("cp.async.cg.shared.global [%0], [%1], 16;" :: "r"(dst), "l"(src))
#define CP_COMMIT() asm volatile("cp.async.commit_group;" ::: "memory")
#define CP_WAIT(n)  asm volatile("cp.async.wait_group %0;" :: "n"(n) : "memory")

__device__ __forceinline__ void ldsm4(uint32_t* r, uint32_t addr) {
    asm volatile("ldmatrix.sync.aligned.m8n8.x4.shared.b16 {%0,%1,%2,%3}, [%4];"
                 : "=r"(r[0]), "=r"(r[1]), "=r"(r[2]), "=r"(r[3]) : "r"(addr));
}

__device__ __forceinline__ void mma_bf16(float* c, const uint32_t* a,
                                         uint32_t b0, uint32_t b1) {
    asm("mma.sync.aligned.m16n8k16.row.col.f32.bf16.bf16.f32 "
        "{%0,%1,%2,%3}, {%4,%5,%6,%7}, {%8,%9}, {%0,%1,%2,%3};"
        : "+f"(c[0]), "+f"(c[1]), "+f"(c[2]), "+f"(c[3])
        : "r"(a[0]), "r"(a[1]), "r"(a[2]), "r"(a[3]), "r"(b0), "r"(b1));
}

__device__ __forceinline__ void split2(float v, bf16& h, bf16& l) {
    h = __float2bfloat16(v);
    l = __float2bfloat16(v - __bfloat162float(h));
}

// ------------------------------------------------------------------
// HMMA GEMM: BM=128, BN=64, BK=32; 256 threads, 8 warps (4m x 2n),
// warp tile 32x32; 3-stage cp.async; 2 CTAs/SM for epilogue overlap.
// D = selected terms of (Ah+Al)·(Bh+Bl)^T.
// ------------------------------------------------------------------
#define A_TB 8192                   // bytes per A tile (128x32 bf16)
#define B_TB 4096                   // bytes per B tile (64x32 bf16)
#define CHUNK (2 * A_TB + 2 * B_TB) // 24576 (Ah Al Bh Bl slots)
#define GEMM_SMEM (3 * CHUNK)       // 73728

enum { EPI_F32_UW = 0, EPI_SPLIT = 1, EPI_BIAS_T_H = 2, EPI_F32_BIAS_RES = 3 };

template <int EPI, int USE_AL, int USE_BL>
__global__ __launch_bounds__(256, 2)
void hmma_gemm(const bf16* __restrict__ Ah, const bf16* __restrict__ Al, int ldA, size_t sA,
               const bf16* __restrict__ Bh, const bf16* __restrict__ Bl, int ldB, size_t sB,
               const float* __restrict__ bias,
               const bf16* __restrict__ resh, const bf16* __restrict__ resl,
               const float* __restrict__ uvec, const float* __restrict__ wvec,
               float* __restrict__ Cf, bf16* __restrict__ Ch, bf16* __restrict__ Cl,
               int ldc, size_t sC, int K) {
    extern __shared__ char sm[];
    uint32_t smu = smem_u32(sm);

    const int tid = threadIdx.x;
    const int w = tid >> 5, lane = tid & 31;
    const int bz = blockIdx.z;
    const int m0 = blockIdx.y * 128;
    const int n0 = blockIdx.x * 64;

    const bf16* pAh = Ah + (size_t)bz * sA + (size_t)m0 * ldA;
    const bf16* pAl = USE_AL ? (Al + (size_t)bz * sA + (size_t)m0 * ldA) : nullptr;
    const bf16* pBh = Bh + (size_t)bz * sB + (size_t)n0 * ldB;
    const bf16* pBl = USE_BL ? (Bl + (size_t)bz * sB + (size_t)n0 * ldB) : nullptr;

    // loader: A = 512 segs (2/thread), B = 256 segs (1/thread)
    const int ar0 = tid >> 2, as0 = tid & 3;                // A seg 1: rows 0..63
    const uint32_t aoff0 = swz64((uint32_t)(ar0 * 64 + as0 * 16));
    const int ar1 = ar0 + 64;                               // A seg 2: rows 64..127
    const uint32_t aoff1 = swz64((uint32_t)(ar1 * 64 + as0 * 16));
    auto load_chunk = [&](int buf, int k0) {
        uint32_t base = smu + (uint32_t)buf * CHUNK;
        CP16(base + aoff0, pAh + (size_t)ar0 * ldA + k0 + as0 * 8);
        CP16(base + aoff1, pAh + (size_t)ar1 * ldA + k0 + as0 * 8);
        if (USE_AL) {
            CP16(base + A_TB + aoff0, pAl + (size_t)ar0 * ldA + k0 + as0 * 8);
            CP16(base + A_TB + aoff1, pAl + (size_t)ar1 * ldA + k0 + as0 * 8);
        }
        CP16(base + 2 * A_TB + aoff0, pBh + (size_t)ar0 * ldB + k0 + as0 * 8);
        if (USE_BL) CP16(base + 2 * A_TB + B_TB + aoff0, pBl + (size_t)ar0 * ldB + k0 + as0 * 8);
    };

    // warps: 4 (m) x 2 (n); warp tile 32 x 32
    const int wm = w >> 1, wn = w & 1;
    const int lr = lane & 7;
    const int r8 = (lane >> 3) & 1;
    const int chi = lane >> 4;

    uint32_t offA[2][2], offB[2][2];
#pragma unroll
    for (int mt = 0; mt < 2; mt++)
#pragma unroll
        for (int ks = 0; ks < 2; ks++)
            offA[mt][ks] = swz64((uint32_t)((wm * 32 + mt * 16 + r8 * 8 + lr) * 64 + (2 * ks + chi) * 16));
#pragma unroll
    for (int nt = 0; nt < 2; nt++)
#pragma unroll
        for (int ks = 0; ks < 2; ks++)
            offB[nt][ks] = swz64((uint32_t)((wn * 32 + nt * 16 + r8 * 8 + lr) * 64 + (2 * ks + chi) * 16));

    float acc[2][4][4];   // [mt][nt*2+nh][quad]
#pragma unroll
    for (int i = 0; i < 2; i++)
#pragma unroll
        for (int j = 0; j < 4; j++)
#pragma unroll
            for (int q = 0; q < 4; q++) acc[i][j][q] = 0.f;

    const int nch = K / 32;
    load_chunk(0, 0);
    CP_COMMIT();
    if (nch > 1) load_chunk(1, 32);
    CP_COMMIT();

    int buf = 0;
    for (int c = 0; c < nch; c++) {
        CP_WAIT(1);
        __syncthreads();

        if (c + 2 < nch) {
            int fb = buf + 2;
            if (fb >= 3) fb -= 3;
            load_chunk(fb, (c + 2) * 32);
        }
        CP_COMMIT();

        uint32_t bu = smu + (uint32_t)buf * CHUNK;
#pragma unroll
        for (int ks = 0; ks < 2; ks++) {
            uint32_t afh[2][4], afl[2][4], bfh[2][4], bfl[2][4];
#pragma unroll
            for (int mt = 0; mt < 2; mt++) {
                ldsm4(afh[mt], bu + offA[mt][ks]);
                if (USE_AL) ldsm4(afl[mt], bu + A_TB + offA[mt][ks]);
            }
#pragma unroll
            for (int nt = 0; nt < 2; nt++) {
                ldsm4(bfh[nt], bu + 2 * A_TB + offB[nt][ks]);
                if (USE_BL) ldsm4(bfl[nt], bu + 2 * A_TB + B_TB + offB[nt][ks]);
            }
#pragma unroll
            for (int mt = 0; mt < 2; mt++)
#pragma unroll
                for (int nt = 0; nt < 2; nt++) {
                    mma_bf16(acc[mt][nt * 2 + 0], afh[mt], bfh[nt][0], bfh[nt][2]);
                    mma_bf16(acc[mt][nt * 2 + 1], afh[mt], bfh[nt][1], bfh[nt][3]);
                }
            if (USE_BL) {
#pragma unroll
                for (int mt = 0; mt < 2; mt++)
#pragma unroll
                    for (int nt = 0; nt < 2; nt++) {
                        mma_bf16(acc[mt][nt * 2 + 0], afh[mt], bfl[nt][0], bfl[nt][2]);
                        mma_bf16(acc[mt][nt * 2 + 1], afh[mt], bfl[nt][1], bfl[nt][3]);
                    }
            }
            if (USE_AL) {
#pragma unroll
                for (int mt = 0; mt < 2; mt++)
#pragma unroll
                    for (int nt = 0; nt < 2; nt++) {
                        mma_bf16(acc[mt][nt * 2 + 0], afl[mt], bfh[nt][0], bfh[nt][2]);
                        mma_bf16(acc[mt][nt * 2 + 1], afl[mt], bfh[nt][1], bfh[nt][3]);
                    }
            }
        }
        buf++;
        if (buf == 3) buf = 0;
    }
    __syncthreads();

    // ---- epilogue: accumulators -> staged smem [128][65] fp32 -> gmem ----
    constexpr int P = 65;
    float* st = (float*)sm;
    {
        int g = lane >> 2, t4 = lane & 3;
#pragma unroll
        for (int mt = 0; mt < 2; mt++) {
            int r = wm * 32 + mt * 16 + g;
#pragma unroll
            for (int j = 0; j < 4; j++) {
                int ccol = wn * 32 + j * 8 + 2 * t4;
                st[r * P + ccol]           = acc[mt][j][0];
                st[r * P + ccol + 1]       = acc[mt][j][1];
                st[(r + 8) * P + ccol]     = acc[mt][j][2];
                st[(r + 8) * P + ccol + 1] = acc[mt][j][3];
            }
        }
    }
    __syncthreads();

    if (EPI == EPI_BIAS_T_H) {
        // transposed h-only store + bias: dest [b][c][t]
#pragma unroll
        for (int it = 0; it < 8; it++) {
            int col = w + 8 * it;
            float bvv = bias[n0 + col];
#pragma unroll
            for (int j = 0; j < 4; j++) {
                int row = lane + 32 * j;
                float v = st[row * P + col] + bvv;
                size_t m = (size_t)m0 + row;
                int bb_ = (int)(m / TT);
                int t = (int)(m % TT);
                Ch[((size_t)bb_ * CC + (n0 + col)) * TT + t] = __float2bfloat16(v);
            }
        }
    } else if (EPI == EPI_F32_UW) {
#pragma unroll
        for (int rr = 0; rr < 16; rr++) {
            int row = w * 16 + rr;
            size_t m = (size_t)m0 + row;
            float um = uvec[(size_t)bz * TT + m];
#pragma unroll
            for (int cb = 0; cb < 2; cb++) {
                int col = lane + 32 * cb;
                float wn_ = wvec[(size_t)bz * TT + n0 + col];
                Cf[(size_t)bz * sC + m * ldc + n0 + col] = st[row * P + col] + um + wn_;
            }
        }
    } else {
#pragma unroll
        for (int rr = 0; rr < 16; rr++) {
            int row = w * 16 + rr;
            size_t m = (size_t)m0 + row;
#pragma unroll
            for (int cb = 0; cb < 2; cb++) {
                int col = lane + 32 * cb;
                float v = st[row * P + col];
                size_t off = (size_t)bz * sC + m * ldc + n0 + col;
                if (EPI == EPI_F32_BIAS_RES) {
                    float r = __bfloat162float(resh[off]) + __bfloat162float(resl[off]);
                    Cf[off] = v + bias[n0 + col] + r;
                } else {  // EPI_SPLIT
                    bf16 h, l; split2(v, h, l);
                    Ch[off] = h;
                    Cl[off] = l;
                }
            }
        }
    }
}

// ------------------------------------------------------------------
// transpose + split + fused u/w rowdots
// ------------------------------------------------------------------
__global__ __launch_bounds__(256)
void transpose_split_fused(const float* __restrict__ x,
                           bf16* __restrict__ rh, bf16* __restrict__ rl,
                           const float* __restrict__ vqk, const float* __restrict__ vkq,
                           float* __restrict__ u, float* __restrict__ wv) {
    __shared__ float tile[32][33];
    int b = blockIdx.z;
    int t0 = blockIdx.x * 32;
    int c0 = blockIdx.y * 32;
    const float* xb = x + (size_t)b * CC * TT;
    size_t ob = (size_t)b * TT * CC;
    int tx = threadIdx.x, ty = threadIdx.y;
#pragma unroll
    for (int i = ty; i < 32; i += 8)
        tile[i][tx] = xb[(size_t)(c0 + i) * TT + t0 + tx];
    __syncthreads();
    float vq = vqk[c0 + tx], vk = vkq[c0 + tx];
#pragma unroll
    for (int i = ty; i < 32; i += 8) {
        float v = tile[tx][i];
        size_t off = ob + (size_t)(t0 + i) * CC + c0 + tx;
        bf16 h, l; split2(v, h, l);
        rh[off] = h;
        rl[off] = l;
        float su = v * vq, sw = v * vk;
#pragma unroll
        for (int o = 16; o; o >>= 1) {
            su += __shfl_xor_sync(0xffffffffu, su, o);
            sw += __shfl_xor_sync(0xffffffffu, sw, o);
        }
        if (tx == 0) {
            atomicAdd(&u[(size_t)b * TT + t0 + i], su);
            atomicAdd(&wv[(size_t)b * TT + t0 + i], sw);
        }
    }
}

__global__ __launch_bounds__(256)
void zero_uw(float* __restrict__ u, float* __restrict__ wv, const float* __restrict__ scal) {
    int i = blockIdx.x * 256 + threadIdx.x;
    u[i] = scal[0];
    wv[i] = 0.f;
}

__global__ __launch_bounds__(256)
void splitW3(const float* __restrict__ Wq, const float* __restrict__ Wk,
             const float* __restrict__ Wv,
             bf16* __restrict__ qh, bf16* __restrict__ ql,
             bf16* __restrict__ kh, bf16* __restrict__ kl,
             bf16* __restrict__ vh, bf16* __restrict__ vl) {
    int i = blockIdx.x * 256 + threadIdx.x;
    bf16 h, l;
    split2(Wq[i], h, l); qh[i] = h; ql[i] = l;
    split2(Wk[i], h, l); kh[i] = h; kl[i] = l;
    split2(Wv[i], h, l); vh[i] = h; vl[i] = l;
}

__global__ __launch_bounds__(256)
void wsplit(const float* __restrict__ W, bf16* __restrict__ Th, bf16* __restrict__ Tl) {
    __shared__ float tile[32][33];
    int k0 = blockIdx.y * 32, n0 = blockIdx.x * 32;
    int tx = threadIdx.x, ty = threadIdx.y;
#pragma unroll
    for (int i = ty; i < 32; i += 8)
        tile[i][tx] = W[(size_t)(k0 + i) * 512 + n0 + tx];
    __syncthreads();
#pragma unroll
    for (int i = ty; i < 32; i += 8) {
        float v = tile[tx][i];
        size_t off = (size_t)(n0 + i) * 512 + k0 + tx;
        bf16 h, l; split2(v, h, l);
        Th[off] = h;
        Tl[off] = l;
    }
}

__global__ void dotk(const float* __restrict__ a, const float* __restrict__ b,
                     float* __restrict__ outscal) {
    int lane = threadIdx.x;
    float s = 0.f;
    for (int i = lane; i < 512; i += 32) s += a[i] * b[i];
#pragma unroll
    for (int o = 16; o; o >>= 1) s += __shfl_xor_sync(0xffffffffu, s, o);
    if (lane == 0) outscal[0] = s;
}

__global__ __launch_bounds__(256)
void matvec2(const float* __restrict__ Wq, const float* __restrict__ bk,
             const float* __restrict__ Wk, const float* __restrict__ bq,
             float* __restrict__ vqk, float* __restrict__ vkq) {
    int c = blockIdx.x * 8 + (threadIdx.x >> 5);
    int lane = threadIdx.x & 31;
    float s1 = 0.f, s2 = 0.f;
    for (int e = lane; e < 512; e += 32) {
        s1 += Wq[(size_t)c * 512 + e] * bk[e];
        s2 += Wk[(size_t)c * 512 + e] * bq[e];
    }
#pragma unroll
    for (int o = 16; o; o >>= 1) {
        s1 += __shfl_xor_sync(0xffffffffu, s1, o);
        s2 += __shfl_xor_sync(0xffffffffu, s2, o);
    }
    if (lane == 0) { vqk[c] = s1; vkq[c] = s2; }
}

__global__ __launch_bounds__(256)
void matvec_row_bf(const bf16* __restrict__ Th, const bf16* __restrict__ Tl,
                   const float* __restrict__ v, float* __restrict__ out) {
    int c = blockIdx.x * 8 + (threadIdx.x >> 5);
    int lane = threadIdx.x & 31;
    float s = 0.f;
    for (int e = lane; e < 512; e += 32) {
        float wv = __bfloat162float(Th[(size_t)c * 512 + e]) +
                   __bfloat162float(Tl[(size_t)c * 512 + e]);
        s += wv * v[e];
    }
#pragma unroll
    for (int o = 16; o; o >>= 1) s += __shfl_xor_sync(0xffffffffu, s, o);
    if (lane == 0) out[c] = s;
}

// ------------------------------------------------------------------
// softmax (in-place fp32) + emit hi bf16
// ------------------------------------------------------------------
__global__ __launch_bounds__(256)
void softmax_split(float* __restrict__ attn, bf16* __restrict__ ah) {
    size_t ro = (size_t)blockIdx.x * TT;
    float* row = attn + ro;
    int t = threadIdx.x;
    float vals[8];
    float m = -1e30f;
#pragma unroll
    for (int j = 0; j < 8; j++) {
        vals[j] = row[t + 256 * j];
        m = fmaxf(m, vals[j]);
    }
#pragma unroll
    for (int o = 16; o; o >>= 1) m = fmaxf(m, __shfl_xor_sync(0xffffffffu, m, o));
    __shared__ float smax[8], ssum[8];
    if ((t & 31) == 0) smax[t >> 5] = m;
    __syncthreads();
    float rm = smax[0];
#pragma unroll
    for (int i = 1; i < 8; i++) rm = fmaxf(rm, smax[i]);

    float s = 0.f;
#pragma unroll
    for (int j = 0; j < 8; j++) {
        vals[j] = expf(vals[j] - rm);
        s += vals[j];
    }
#pragma unroll
    for (int o = 16; o; o >>= 1) s += __shfl_xor_sync(0xffffffffu, s, o);
    if ((t & 31) == 0) ssum[t >> 5] = s;
    __syncthreads();
    float tot = 0.f;
#pragma unroll
    for (int i = 0; i < 8; i++) tot += ssum[i];
    float inv = 1.f / tot;

#pragma unroll
    for (int j = 0; j < 8; j++) {
        float v = vals[j] * inv;
        row[t + 256 * j] = v;
        ah[ro + t + 256 * j] = __float2bfloat16(v);
    }
}

// ------------------------------------------------------------------
// LayerNorm over C=512
// ------------------------------------------------------------------
__global__ __launch_bounds__(128)
void ln_kernel(const float* __restrict__ h, const float* __restrict__ gamma,
               const float* __restrict__ beta, float* __restrict__ out) {
    const float* hr = h + (size_t)blockIdx.x * CC;
    int t = threadIdx.x;
    float4 v = ((const float4*)hr)[t];

    float s = v.x + v.y + v.z + v.w;
#pragma unroll
    for (int o = 16; o; o >>= 1) s += __shfl_xor_sync(0xffffffffu, s, o);
    __shared__ float s1[4], s2[4];
    if ((t & 31) == 0) s1[t >> 5] = s;
    __syncthreads();
    float mu = (s1[0] + s1[1] + s1[2] + s1[3]) * (1.f / CC);

    float dx = v.x - mu, dy = v.y - mu, dz = v.z - mu, dw = v.w - mu;
    float q = dx * dx + dy * dy + dz * dz + dw * dw;
#pragma unroll
    for (int o = 16; o; o >>= 1) q += __shfl_xor_sync(0xffffffffu, q, o);
    if ((t & 31) == 0) s2[t >> 5] = q;
    __syncthreads();
    float var = (s2[0] + s2[1] + s2[2] + s2[3]) * (1.f / CC);
    float inv = rsqrtf(var + LN_EPS);

    float4 g = ((const float4*)gamma)[t];
    float4 b = ((const float4*)beta)[t];
    float4 o4;
    o4.x = dx * inv * g.x + b.x;
    o4.y = dy * inv * g.y + b.y;
    o4.z = dz * inv * g.z + b.z;
    o4.w = dw * inv * g.w + b.w;
    ((float4*)(out + (size_t)blockIdx.x * CC))[t] = o4;
}

// ------------------------------------------------------------------
// launch
// ------------------------------------------------------------------
extern "C" void kernel_launch(void* const* d_in, const int* in_sizes, int n_in,
                              void* d_out, int out_size) {
    const float* x     = (const float*)d_in[0];
    const float* Wq    = (const float*)d_in[1];
    const float* bq    = (const float*)d_in[2];
    const float* Wk    = (const float*)d_in[3];
    const float* bk    = (const float*)d_in[4];
    const float* Wv    = (const float*)d_in[5];
    const float* bv    = (const float*)d_in[6];
    const float* Wo    = (const float*)d_in[7];
    const float* bo    = (const float*)d_in[8];
    const float* gamma = (const float*)d_in[9];
    const float* beta  = (const float*)d_in[10];

    float* out = (float*)d_out;
    float* attn = out;
    float* final_out = out + (size_t)BB * TT * TT;

    float *hbuf, *vqk, *vkq, *bvo, *uv, *wv_, *scal;
    bf16 *rh, *rl, *qmh, *qml, *vth, *anh;
    bf16 *wqh, *wql, *wkh, *wkl, *wvh, *wvl, *woh, *wol;
    bf16 *mth, *mtl, *nth, *ntl;
    cudaGetSymbolAddress((void**)&hbuf, g_h);
    cudaGetSymbolAddress((void**)&rh, g_resid_h);
    cudaGetSymbolAddress((void**)&rl, g_resid_l);
    cudaGetSymbolAddress((void**)&qmh, g_qm_h);
    cudaGetSymbolAddress((void**)&qml, g_qm_l);
    cudaGetSymbolAddress((void**)&vth, g_vt_h);
    cudaGetSymbolAddress((void**)&anh, g_attn_h);
    cudaGetSymbolAddress((void**)&wqh, g_wq_h);
    cudaGetSymbolAddress((void**)&wql, g_wq_l);
    cudaGetSymbolAddress((void**)&wkh, g_wk_h);
    cudaGetSymbolAddress((void**)&wkl, g_wk_l);
    cudaGetSymbolAddress((void**)&wvh, g_wv_h);
    cudaGetSymbolAddress((void**)&wvl, g_wv_l);
    cudaGetSymbolAddress((void**)&woh, g_woT_h);
    cudaGetSymbolAddress((void**)&wol, g_woT_l);
    cudaGetSymbolAddress((void**)&mth, g_MT_h);
    cudaGetSymbolAddress((void**)&mtl, g_MT_l);
    cudaGetSymbolAddress((void**)&nth, g_NT_h);
    cudaGetSymbolAddress((void**)&ntl, g_NT_l);
    cudaGetSymbolAddress((void**)&vqk, g_vqk);
    cudaGetSymbolAddress((void**)&vkq, g_vkq);
    cudaGetSymbolAddress((void**)&bvo, g_bvo);
    cudaGetSymbolAddress((void**)&uv, g_u);
    cudaGetSymbolAddress((void**)&wv_, g_w);
    cudaGetSymbolAddress((void**)&scal, g_scal);

    cudaFuncSetAttribute(hmma_gemm<EPI_SPLIT, 1, 1>,        cudaFuncAttributeMaxDynamicSharedMemorySize, GEMM_SMEM);
    cudaFuncSetAttribute(hmma_gemm<EPI_F32_UW, 1, 1>,       cudaFuncAttributeMaxDynamicSharedMemorySize, GEMM_SMEM);
    cudaFuncSetAttribute(hmma_gemm<EPI_BIAS_T_H, 0, 0>,     cudaFuncAttributeMaxDynamicSharedMemorySize, GEMM_SMEM);
    cudaFuncSetAttribute(hmma_gemm<EPI_F32_BIAS_RES, 0, 0>, cudaFuncAttributeMaxDynamicSharedMemorySize, GEMM_SMEM);

    // ---- prep: bias vectors first (transpose consumes vqk/vkq) ----
    dotk<<<1, 32>>>(bq, bk, scal);
    zero_uw<<<(BB * TT) / 256, 256>>>(uv, wv_, scal);
    matvec2<<<64, 256>>>(Wq, bk, Wk, bq, vqk, vkq);

    // transpose + split + fused u/w rowdots
    transpose_split_fused<<<dim3(TT / 32, CC / 32, BB), dim3(32, 8)>>>(
        x, rh, rl, vqk, vkq, uv, wv_);

    // weight splits
    splitW3<<<1024, 256>>>(Wq, Wk, Wv, wqh, wql, wkh, wkl, wvh, wvl);
    wsplit<<<dim3(16, 16), dim3(32, 8)>>>(Wo, woh, wol);
    matvec_row_bf<<<64, 256>>>(woh, wol, bv, bvo);

    // MT = Wk @ Wq^T, NT = Wo^T @ Wv^T — tiny 3-term GEMMs (BN=64)
    hmma_gemm<EPI_SPLIT, 1, 1><<<dim3(8, 4, 1), 256, GEMM_SMEM>>>(
        wkh, wkl, EE, 0, wqh, wql, EE, 0, nullptr, nullptr, nullptr, nullptr, nullptr,
        nullptr, mth, mtl, CC, 0, EE);
    hmma_gemm<EPI_SPLIT, 1, 1><<<dim3(8, 4, 1), 256, GEMM_SMEM>>>(
        woh, wol, EE, 0, wvh, wvl, EE, 0, nullptr, nullptr, nullptr, nullptr, nullptr,
        nullptr, nth, ntl, CC, 0, EE);

    // qm = resid @ M  (3-term)
    hmma_gemm<EPI_SPLIT, 1, 1><<<dim3(CC / 64, (BB * TT) / 128, 1), 256, GEMM_SMEM>>>(
        rh, rl, CC, 0, mth, mtl, CC, 0, nullptr, nullptr, nullptr, nullptr, nullptr,
        nullptr, qmh, qml, CC, 0, CC);

    // energy = qm @ resid^T + u[t] + w[s]  (3-term)
    hmma_gemm<EPI_F32_UW, 1, 1><<<dim3(TT / 64, TT / 128, BB), 256, GEMM_SMEM>>>(
        qmh, qml, CC, (size_t)TT * CC, rh, rl, CC, (size_t)TT * CC,
        nullptr, nullptr, nullptr, uv, wv_,
        attn, nullptr, nullptr, TT, (size_t)TT * TT, CC);

    // softmax in-place + emit hi bf16
    softmax_split<<<BB * TT, 256>>>(attn, anh);

    // vw = resid @ N + bvo  (1-term, transposed h-only out)
    hmma_gemm<EPI_BIAS_T_H, 0, 0><<<dim3(CC / 64, (BB * TT) / 128, 1), 256, GEMM_SMEM>>>(
        rh, nullptr, CC, 0, nth, nullptr, CC, 0, bvo, nullptr, nullptr, nullptr, nullptr,
        nullptr, vth, nullptr, CC, 0, CC);

    // h = attn_h @ vw^T + bo + (rh+rl)  (1-term)
    hmma_gemm<EPI_F32_BIAS_RES, 0, 0><<<dim3(CC / 64, TT / 128, BB), 256, GEMM_SMEM>>>(
        anh, nullptr, TT, (size_t)TT * TT, vth, nullptr, TT, (size_t)CC * TT,
        bo, rh, rl, nullptr, nullptr,
        hbuf, nullptr, nullptr, CC, (size_t)TT * CC, TT);

    // LayerNorm -> final output region
    ln_kernel<<<BB * TT, 128>>>(hbuf, gamma, beta, final_out);
}